// round 4
// baseline (speedup 1.0000x reference)
#include <cuda_runtime.h>
#include <math.h>

#define BB   256
#define TT   128
#define EE   100
#define HH   100
#define CC   255
#define MLPD 300
#define MROWS 32768        // B*T
#define NPAD 1024

typedef unsigned long long ULL;

__device__ __forceinline__ void ffma2(ULL& acc, ULL a, ULL b) {
    asm volatile("fma.rn.f32x2 %0, %1, %2, %0;" : "+l"(acc) : "l"(a), "l"(b));
}
__device__ __forceinline__ ULL pack2(float x, float y) {
    ULL r; asm("mov.b64 %0, {%1,%2};" : "=l"(r) : "f"(x), "f"(y)); return r;
}
__device__ __forceinline__ float2 unpack2(ULL v) {
    float2 r; asm("mov.b64 {%0,%1}, %2;" : "=f"(r.x), "=f"(r.y) : "l"(v)); return r;
}
__device__ __forceinline__ float tanhf_fast(float x) {
    float r; asm("tanh.approx.f32 %0, %1;" : "=f"(r) : "f"(x)); return r;
}
__device__ __forceinline__ float sigf(float x) { return 0.5f * tanhf_fast(0.5f * x) + 0.5f; }

// ---------------- device-global scratch ----------------------------------------
__device__ ULL   d_xeT[100 * MROWS];        // dup pairs, [k][r], r=t*256+b
__device__ float d_WtIn[100 * NPAD];        // [k][col] col<800 valid (400 fwd | 400 bwd)
__device__ float d_bsum[NPAD];
__device__ float d_gin[MROWS * NPAD];       // [r=t*256+b][col] col = dir*400 + gate*100 + hid
__device__ ULL   d_h2T[200 * MROWS];        // dup pairs, [k=dir*100+hid][r=b*128+t]
__device__ float d_WtS[200 * NPAD];         // [k][s*300+m], cols>=900 zero
__device__ float d_S[MROWS * NPAD];         // [r=b*128+t][col]

// ---------------- prep ----------------------------------------------------------
__global__ void prep_k(const float* __restrict__ Wih_f, const float* __restrict__ Wih_b,
                       const float* __restrict__ bih_f, const float* __restrict__ bhh_f,
                       const float* __restrict__ bih_b, const float* __restrict__ bhh_b,
                       const float* __restrict__ W1) {
    int stride = gridDim.x * blockDim.x;
    int i0 = blockIdx.x * blockDim.x + threadIdx.x;
    for (int idx = i0; idx < 100 * NPAD; idx += stride) {
        int k = idx / NPAD, col = idx % NPAD;
        float v = 0.0f;
        if (col < 400)      v = Wih_f[col * 100 + k];
        else if (col < 800) v = Wih_b[(col - 400) * 100 + k];
        d_WtIn[idx] = v;
    }
    for (int idx = i0; idx < NPAD; idx += stride) {
        float v = 0.0f;
        if (idx < 400)      v = bih_f[idx] + bhh_f[idx];
        else if (idx < 800) v = bih_b[idx - 400] + bhh_b[idx - 400];
        d_bsum[idx] = v;
    }
    for (int idx = i0; idx < 200 * NPAD; idx += stride) {
        int k = idx / NPAD, col = idx % NPAD;
        float v = 0.0f;
        if (col < 900) {
            int s = col / MLPD, m = col % MLPD;
            v = W1[(s * 200 + k) * MLPD + m];
        }
        d_WtS[idx] = v;
    }
}

// ---------------- embed gather + transpose + duplicate --------------------------
__global__ __launch_bounds__(512) void xet_k(const int* __restrict__ x,
                                             const float* __restrict__ emb) {
    __shared__ float sh[128][101];
    __shared__ int toks[128];
    const int tid = threadIdx.x;
    const int r0 = blockIdx.x * 128;
    if (tid < 128) {
        int r = r0 + tid;
        toks[tid] = x[(r & 255) * TT + (r >> 8)];   // r = t*256+b
    }
    __syncthreads();
    for (int idx = tid; idx < 128 * 100; idx += 512) {
        int row = idx / 100, k = idx % 100;
        sh[row][k] = emb[(long)toks[row] * EE + k];
    }
    __syncthreads();
    for (int idx = tid; idx < 100 * 128; idx += 512) {
        int k = idx >> 7, j = idx & 127;
        float v = sh[j][k];
        d_xeT[(long)k * MROWS + r0 + j] = pack2(v, v);
    }
}

// ---------------- GEMM: C[M, cols of NC] = A_dup^T @ B (+bias) ------------------
// BM=128, BN=128, BK=20, 512 threads, TM=8, TN=4, f32x2, reg-prefetch dbl buffer.
// Last col-tile overlaps (c0 = min(by*128, NC-128)); overlap rows written twice
// with identical values (benign).
template <int KT, bool BIAS>
__device__ __forceinline__ void gemm_body(const ULL* __restrict__ Adup,
                                          const float* __restrict__ Bw,
                                          const float* __restrict__ bias,
                                          float* __restrict__ Cout, int NC) {
    __shared__ __align__(16) ULL   As[20][128];
    __shared__ __align__(16) float Bs[20][128];
    const int tid = threadIdx.x;
    const int tx = tid & 31;
    const int ty = tid >> 5;
    const int r0 = blockIdx.x * 128;
    const int c0 = min((int)blockIdx.y * 128, NC - 128);

    ULL acc[8][2];
    if (BIAS) {
        ulonglong2 bp = *(const ulonglong2*)&bias[c0 + tx * 4];
#pragma unroll
        for (int i = 0; i < 8; i++) { acc[i][0] = bp.x; acc[i][1] = bp.y; }
    } else {
#pragma unroll
        for (int i = 0; i < 8; i++) { acc[i][0] = 0ull; acc[i][1] = 0ull; }
    }

    ULL apf[5]; float bpf[5];
#pragma unroll
    for (int j = 0; j < 5; j++) {
        int idx = tid + 512 * j;
        int kk = idx >> 7, rr = idx & 127;
        apf[j] = Adup[(long)kk * MROWS + r0 + rr];
        bpf[j] = Bw[kk * NPAD + c0 + rr];
    }

    for (int kt = 0; kt < KT; kt++) {
#pragma unroll
        for (int j = 0; j < 5; j++) {
            int idx = tid + 512 * j;
            int kk = idx >> 7, rr = idx & 127;
            As[kk][rr] = apf[j];
            Bs[kk][rr] = bpf[j];
        }
        __syncthreads();
        if (kt + 1 < KT) {
            int kbase = (kt + 1) * 20;
#pragma unroll
            for (int j = 0; j < 5; j++) {
                int idx = tid + 512 * j;
                int kk = idx >> 7, rr = idx & 127;
                apf[j] = Adup[(long)(kbase + kk) * MROWS + r0 + rr];
                bpf[j] = Bw[(kbase + kk) * NPAD + c0 + rr];
            }
        }
#pragma unroll
        for (int kk = 0; kk < 20; kk++) {
            ulonglong2 bp = *(const ulonglong2*)&Bs[kk][tx * 4];
#pragma unroll
            for (int i2 = 0; i2 < 4; i2++) {
                ulonglong2 a2 = *(const ulonglong2*)&As[kk][ty * 8 + i2 * 2];
                ffma2(acc[i2 * 2][0],     a2.x, bp.x);
                ffma2(acc[i2 * 2][1],     a2.x, bp.y);
                ffma2(acc[i2 * 2 + 1][0], a2.y, bp.x);
                ffma2(acc[i2 * 2 + 1][1], a2.y, bp.y);
            }
        }
        __syncthreads();
    }
#pragma unroll
    for (int i = 0; i < 8; i++) {
        float2 v0 = unpack2(acc[i][0]);
        float2 v1 = unpack2(acc[i][1]);
        *(float4*)&Cout[(long)(r0 + ty * 8 + i) * NPAD + c0 + tx * 4] =
            make_float4(v0.x, v0.y, v1.x, v1.y);
    }
}

__global__ __launch_bounds__(512) void gates_gemm_k() {
    gemm_body<5, true>(d_xeT, d_WtIn, d_bsum, d_gin, 800);
}
__global__ __launch_bounds__(512) void s_gemm_k() {
    gemm_body<10, false>(d_h2T, d_WtS, nullptr, d_S, 900);
}

// ---------------- LSTM recurrence: K-split, no spills, gin prefetch --------------
// 128 blocks: dir = blk>>6, batch base = (blk&63)*4. 800 threads:
//   phase 1: thread = (j = tid%400 gate-row, half = tid/400 k-half), 4 batches,
//            Whh half-row (25 ULL pairs) in registers; partials -> psh.
//   phase 2: threads tid<400 = (b = tid/100, hid = tid%100): finalize gates,
//            cell update, write h to smem (padded half layout) + d_h2T.
__global__ __launch_bounds__(800, 1) void lstm_k(const float* __restrict__ Whh_f,
                                                 const float* __restrict__ Whh_b) {
    __shared__ __align__(16) float hs[8 * 56];     // [b*2+half][56], 50 used per half
    __shared__ float psh[8 * 400];                 // [half*4+b][j]
    const int tid = threadIdx.x;
    const int dir = blockIdx.x >> 6;
    const int b0 = (blockIdx.x & 63) * 4;
    const float* __restrict__ Whh = dir ? Whh_b : Whh_f;

    const int half = (tid >= 400) ? 1 : 0;
    const int j = tid - half * 400;

    ULL wreg[25];
    {
        const ULL* row = (const ULL*)(Whh + j * 100 + half * 50);
#pragma unroll
        for (int kk = 0; kk < 25; kk++) wreg[kk] = row[kk];
    }
    for (int idx = tid; idx < 8 * 56; idx += 800) hs[idx] = 0.0f;

    // phase-2 persistent state
    const int pb = tid / 100;       // batch (valid tid<400)
    const int hid = tid - pb * 100;
    float c = 0.0f;
    float g0 = 0.f, g1 = 0.f, g2 = 0.f, g3 = 0.f;
    if (tid < 400) {
        int t0 = dir ? (TT - 1) : 0;
        const float* gp = &d_gin[((long)(t0 * 256 + b0 + pb)) * NPAD + dir * 400 + hid];
        g0 = gp[0]; g1 = gp[100]; g2 = gp[200]; g3 = gp[300];
    }
    __syncthreads();

    for (int step = 0; step < TT; ++step) {
        const int t = dir ? (TT - 1 - step) : step;

        // ---- phase 1: partial matvec over this thread's 50 k-values ----
#pragma unroll
        for (int b = 0; b < 4; b++) {
            const float* hb = &hs[(b * 2 + half) * 56];
            ULL a0 = 0ull, a1 = 0ull;
#pragma unroll
            for (int kk2 = 0; kk2 < 6; kk2++) {
                ulonglong2 h0 = *(const ulonglong2*)(hb + 8 * kk2);
                ulonglong2 h1 = *(const ulonglong2*)(hb + 8 * kk2 + 4);
                ffma2(a0, wreg[4 * kk2],     h0.x);
                ffma2(a1, wreg[4 * kk2 + 1], h0.y);
                ffma2(a0, wreg[4 * kk2 + 2], h1.x);
                ffma2(a1, wreg[4 * kk2 + 3], h1.y);
            }
            {   // tail: float idx 48..49 = pair 24
                ULL h1 = *(const ULL*)(hb + 48);
                ffma2(a0, wreg[24], h1);
            }
            float2 fa = unpack2(a0), fb = unpack2(a1);
            psh[(half * 4 + b) * 400 + j] = fa.x + fa.y + fb.x + fb.y;
        }
        __syncthreads();

        // ---- phase 2: gate finalize + cell update ----
        if (tid < 400) {
            float pi = g0 + psh[pb * 400 + hid]       + psh[(4 + pb) * 400 + hid];
            float pf = g1 + psh[pb * 400 + 100 + hid] + psh[(4 + pb) * 400 + 100 + hid];
            float pg = g2 + psh[pb * 400 + 200 + hid] + psh[(4 + pb) * 400 + 200 + hid];
            float po = g3 + psh[pb * 400 + 300 + hid] + psh[(4 + pb) * 400 + 300 + hid];
            c = sigf(pf) * c + sigf(pi) * tanhf_fast(pg);
            float h = sigf(po) * tanhf_fast(c);
            int hh = (hid >= 50) ? 1 : 0;
            hs[(pb * 2 + hh) * 56 + hid - hh * 50] = h;
            d_h2T[(long)(dir * 100 + hid) * MROWS + (b0 + pb) * TT + t] = pack2(h, h);

            // prefetch next step's gin
            int sn = (step + 1 < TT) ? (step + 1) : step;
            int tn = dir ? (TT - 1 - sn) : sn;
            const float* gp = &d_gin[((long)(tn * 256 + b0 + pb)) * NPAD + dir * 400 + hid];
            g0 = gp[0]; g1 = gp[100]; g2 = gp[200]; g3 = gp[300];
        }
        __syncthreads();
    }
}

// ---------------- combine: gather + tanh + (300->3) + softmax --------------------
__global__ __launch_bounds__(256) void combine_k(const int* __restrict__ paths,
                                                 const float* __restrict__ b1,
                                                 const float* __restrict__ W2,
                                                 const float* __restrict__ b2,
                                                 float* __restrict__ out) {
    const int warp = (blockIdx.x * blockDim.x + threadIdx.x) >> 5;
    const int lane = threadIdx.x & 31;
    if (warp >= BB * CC) return;
    const int b = warp / CC;

    const int* p = &paths[warp * 3];
    int p0 = __ldg(p), p1 = __ldg(p + 1), p2 = __ldg(p + 2);
    int i0 = min(max(p0, 0), TT - 1);
    int i1 = min(max(p1, 0), TT - 1);
    int i2 = min(max(p2, 0), TT - 1);

    const float* S0 = &d_S[(long)(b * TT + i0) * NPAD];
    const float* S1 = &d_S[(long)(b * TT + i1) * NPAD + 300];
    const float* S2 = &d_S[(long)(b * TT + i2) * NPAD + 600];

    float z0 = 0.f, z1 = 0.f, z2 = 0.f;
    for (int m = lane; m < MLPD; m += 32) {
        float hv = __ldg(&b1[m]);
        if (p0 >= 0) hv += S0[m];
        if (p1 >= 0) hv += S1[m];
        if (p2 >= 0) hv += S2[m];
        hv = tanhf_fast(hv);
        z0 = fmaf(hv, __ldg(&W2[m * 3 + 0]), z0);
        z1 = fmaf(hv, __ldg(&W2[m * 3 + 1]), z1);
        z2 = fmaf(hv, __ldg(&W2[m * 3 + 2]), z2);
    }
#pragma unroll
    for (int off = 16; off; off >>= 1) {
        z0 += __shfl_xor_sync(0xFFFFFFFFu, z0, off);
        z1 += __shfl_xor_sync(0xFFFFFFFFu, z1, off);
        z2 += __shfl_xor_sync(0xFFFFFFFFu, z2, off);
    }
    if (lane == 0) {
        z0 += __ldg(&b2[0]); z1 += __ldg(&b2[1]); z2 += __ldg(&b2[2]);
        float mx = fmaxf(z0, fmaxf(z1, z2));
        float e0 = __expf(z0 - mx), e1 = __expf(z1 - mx), e2 = __expf(z2 - mx);
        float inv = 1.0f / (e0 + e1 + e2);
        out[warp * 3 + 0] = e0 * inv;
        out[warp * 3 + 1] = e1 * inv;
        out[warp * 3 + 2] = e2 * inv;
    }
}

// -------------------------------- launch -----------------------------------------
extern "C" void kernel_launch(void* const* d_in, const int* in_sizes, int n_in,
                              void* d_out, int out_size) {
    const int*   x     = (const int*)  d_in[0];
    const int*   paths = (const int*)  d_in[1];
    const float* emb   = (const float*)d_in[2];
    const float* Whh_f = (const float*)d_in[4];
    const float* Whh_b = (const float*)d_in[8];
    const float* W1    = (const float*)d_in[11];
    const float* b1    = (const float*)d_in[12];
    const float* W2    = (const float*)d_in[13];
    const float* b2    = (const float*)d_in[14];
    float* out = (float*)d_out;

    prep_k<<<128, 256>>>((const float*)d_in[3], (const float*)d_in[7],
                         (const float*)d_in[5], (const float*)d_in[6],
                         (const float*)d_in[9], (const float*)d_in[10], W1);

    xet_k<<<256, 512>>>(x, emb);

    { dim3 g(256, 7); gates_gemm_k<<<g, 512>>>(); }   // 800 cols, last tile overlapped

    lstm_k<<<128, 800>>>(Whh_f, Whh_b);

    { dim3 g(256, 8); s_gemm_k<<<g, 512>>>(); }       // 900 cols, last tile overlapped

    {
        int warps = BB * CC;
        int blocks = (warps * 32 + 255) / 256;
        combine_k<<<blocks, 256>>>(paths, b1, W2, b2, out);
    }
}

// round 5
// speedup vs baseline: 1.1007x; 1.1007x over previous
#include <cuda_runtime.h>
#include <math.h>

#define BB   256
#define TT   128
#define EE   100
#define HH   100
#define CC   255
#define MLPD 300
#define MROWS 32768        // B*T
#define NPAD 1024

typedef unsigned long long ULL;

__device__ __forceinline__ void ffma2(ULL& acc, ULL a, ULL b) {
    asm volatile("fma.rn.f32x2 %0, %1, %2, %0;" : "+l"(acc) : "l"(a), "l"(b));
}
__device__ __forceinline__ ULL pack2(float x, float y) {
    ULL r; asm("mov.b64 %0, {%1,%2};" : "=l"(r) : "f"(x), "f"(y)); return r;
}
__device__ __forceinline__ float2 unpack2(ULL v) {
    float2 r; asm("mov.b64 {%0,%1}, %2;" : "=f"(r.x), "=f"(r.y) : "l"(v)); return r;
}
__device__ __forceinline__ float tanhf_fast(float x) {
    float r; asm("tanh.approx.f32 %0, %1;" : "=f"(r) : "f"(x)); return r;
}
__device__ __forceinline__ float sigf(float x) { return 0.5f * tanhf_fast(0.5f * x) + 0.5f; }

// ---------------- device-global scratch ----------------------------------------
__device__ ULL   d_xeT[100 * MROWS];        // dup pairs, [k][r], r=t*256+b
__device__ float d_WtIn[100 * NPAD];        // [k][col] col<800 valid (400 fwd | 400 bwd)
__device__ float d_bsum[NPAD];
__device__ float d_gin[MROWS * NPAD];       // [r=t*256+b][col] col = dir*400 + gate*100 + hid
__device__ ULL   d_h2T[200 * MROWS];        // dup pairs, [k=dir*100+hid][r=b*128+t]
__device__ float d_WtS[200 * NPAD];         // [k][s*300+m], cols>=900 zero
__device__ float d_S[MROWS * NPAD];         // [r=b*128+t][col]

// ---------------- prep ----------------------------------------------------------
__global__ void prep_k(const float* __restrict__ Wih_f, const float* __restrict__ Wih_b,
                       const float* __restrict__ bih_f, const float* __restrict__ bhh_f,
                       const float* __restrict__ bih_b, const float* __restrict__ bhh_b,
                       const float* __restrict__ W1) {
    int stride = gridDim.x * blockDim.x;
    int i0 = blockIdx.x * blockDim.x + threadIdx.x;
    for (int idx = i0; idx < 100 * NPAD; idx += stride) {
        int k = idx / NPAD, col = idx % NPAD;
        float v = 0.0f;
        if (col < 400)      v = Wih_f[col * 100 + k];
        else if (col < 800) v = Wih_b[(col - 400) * 100 + k];
        d_WtIn[idx] = v;
    }
    for (int idx = i0; idx < NPAD; idx += stride) {
        float v = 0.0f;
        if (idx < 400)      v = bih_f[idx] + bhh_f[idx];
        else if (idx < 800) v = bih_b[idx - 400] + bhh_b[idx - 400];
        d_bsum[idx] = v;
    }
    for (int idx = i0; idx < 200 * NPAD; idx += stride) {
        int k = idx / NPAD, col = idx % NPAD;
        float v = 0.0f;
        if (col < 900) {
            int s = col / MLPD, m = col % MLPD;
            v = W1[(s * 200 + k) * MLPD + m];
        }
        d_WtS[idx] = v;
    }
}

// ---------------- embed gather + transpose + duplicate --------------------------
__global__ __launch_bounds__(512) void xet_k(const int* __restrict__ x,
                                             const float* __restrict__ emb) {
    __shared__ float sh[128][101];
    __shared__ int toks[128];
    const int tid = threadIdx.x;
    const int r0 = blockIdx.x * 128;
    if (tid < 128) {
        int r = r0 + tid;
        toks[tid] = x[(r & 255) * TT + (r >> 8)];   // r = t*256+b
    }
    __syncthreads();
    for (int idx = tid; idx < 128 * 100; idx += 512) {
        int row = idx / 100, k = idx % 100;
        sh[row][k] = emb[(long)toks[row] * EE + k];
    }
    __syncthreads();
    for (int idx = tid; idx < 100 * 128; idx += 512) {
        int k = idx >> 7, j = idx & 127;
        float v = sh[j][k];
        d_xeT[(long)k * MROWS + r0 + j] = pack2(v, v);
    }
}

// ---------------- GEMM: C[M, cols of NC] = A_dup^T @ B (+bias) ------------------
template <int KT, bool BIAS>
__device__ __forceinline__ void gemm_body(const ULL* __restrict__ Adup,
                                          const float* __restrict__ Bw,
                                          const float* __restrict__ bias,
                                          float* __restrict__ Cout, int NC) {
    __shared__ __align__(16) ULL   As[20][128];
    __shared__ __align__(16) float Bs[20][128];
    const int tid = threadIdx.x;
    const int tx = tid & 31;
    const int ty = tid >> 5;
    const int r0 = blockIdx.x * 128;
    const int c0 = min((int)blockIdx.y * 128, NC - 128);

    ULL acc[8][2];
    if (BIAS) {
        ulonglong2 bp = *(const ulonglong2*)&bias[c0 + tx * 4];
#pragma unroll
        for (int i = 0; i < 8; i++) { acc[i][0] = bp.x; acc[i][1] = bp.y; }
    } else {
#pragma unroll
        for (int i = 0; i < 8; i++) { acc[i][0] = 0ull; acc[i][1] = 0ull; }
    }

    ULL apf[5]; float bpf[5];
#pragma unroll
    for (int j = 0; j < 5; j++) {
        int idx = tid + 512 * j;
        int kk = idx >> 7, rr = idx & 127;
        apf[j] = Adup[(long)kk * MROWS + r0 + rr];
        bpf[j] = Bw[kk * NPAD + c0 + rr];
    }

    for (int kt = 0; kt < KT; kt++) {
#pragma unroll
        for (int j = 0; j < 5; j++) {
            int idx = tid + 512 * j;
            int kk = idx >> 7, rr = idx & 127;
            As[kk][rr] = apf[j];
            Bs[kk][rr] = bpf[j];
        }
        __syncthreads();
        if (kt + 1 < KT) {
            int kbase = (kt + 1) * 20;
#pragma unroll
            for (int j = 0; j < 5; j++) {
                int idx = tid + 512 * j;
                int kk = idx >> 7, rr = idx & 127;
                apf[j] = Adup[(long)(kbase + kk) * MROWS + r0 + rr];
                bpf[j] = Bw[(kbase + kk) * NPAD + c0 + rr];
            }
        }
#pragma unroll
        for (int kk = 0; kk < 20; kk++) {
            ulonglong2 bp = *(const ulonglong2*)&Bs[kk][tx * 4];
#pragma unroll
            for (int i2 = 0; i2 < 4; i2++) {
                ulonglong2 a2 = *(const ulonglong2*)&As[kk][ty * 8 + i2 * 2];
                ffma2(acc[i2 * 2][0],     a2.x, bp.x);
                ffma2(acc[i2 * 2][1],     a2.x, bp.y);
                ffma2(acc[i2 * 2 + 1][0], a2.y, bp.x);
                ffma2(acc[i2 * 2 + 1][1], a2.y, bp.y);
            }
        }
        __syncthreads();
    }
#pragma unroll
    for (int i = 0; i < 8; i++) {
        float2 v0 = unpack2(acc[i][0]);
        float2 v1 = unpack2(acc[i][1]);
        *(float4*)&Cout[(long)(r0 + ty * 8 + i) * NPAD + c0 + tx * 4] =
            make_float4(v0.x, v0.y, v1.x, v1.y);
    }
}

__global__ __launch_bounds__(512) void gates_gemm_k() {
    gemm_body<5, true>(d_xeT, d_WtIn, d_bsum, d_gin, 800);
}
__global__ __launch_bounds__(512) void s_gemm_k() {
    gemm_body<10, false>(d_h2T, d_WtS, nullptr, d_S, 900);
}

// ---------------- LSTM recurrence: 4-gates-per-thread, quarter-K split -----------
// 128 blocks: dir = blk>>6, batch base = (blk&63)*4. 400 threads:
//   thread = (hid = tid%100, q = tid/100): owns gate rows {g*100+hid} for all 4
//   gates over k in [q*25, q*25+25). Weights: 4x13 ULL pairs = 104 regs.
//   h stored per batch in quarter-padded layout: hs[b*116 + q*28 + i], i<25 data,
//   i>=25 zero (so the tail ULL load pairs (h24, 0)).
//   Phase 1 -> psh[(q*4+b)*400 + g*100 + hid]; phase 2: 4-way reduce + cell update.
__global__ __launch_bounds__(400, 1) void lstm_k(const float* __restrict__ Whh_f,
                                                 const float* __restrict__ Whh_b) {
    __shared__ __align__(16) float hs[4 * 116];    // [b][q*28+i]
    __shared__ float psh[16 * 400];                // [(q*4+b)][row]
    const int tid = threadIdx.x;
    const int dir = blockIdx.x >> 6;
    const int b0 = (blockIdx.x & 63) * 4;
    const float* __restrict__ Whh = dir ? Whh_b : Whh_f;

    const int hid = tid % 100;
    const int q = tid / 100;

    // Pack weights: w[g][p] = (Whh[g*100+hid][q*25+2p], Whh[...][q*25+2p+1]), p12=(w24,0)
    ULL w[4][13];
#pragma unroll
    for (int g = 0; g < 4; g++) {
        const float* row = Whh + (g * 100 + hid) * 100 + q * 25;
#pragma unroll
        for (int p = 0; p < 12; p++) w[g][p] = pack2(row[2 * p], row[2 * p + 1]);
        w[g][12] = pack2(row[24], 0.0f);
    }
    for (int idx = tid; idx < 4 * 116; idx += 400) hs[idx] = 0.0f;

    // phase-2 persistent state (thread = (pb, hid2))
    const int pb = tid / 100;         // same partition as q, reused as batch
    const int hq = hid / 25, hr = hid % 25;   // h store slot
    float c = 0.0f;
    float g0 = 0.f, g1 = 0.f, g2 = 0.f, g3 = 0.f;
    {
        int t0 = dir ? (TT - 1) : 0;
        const float* gp = &d_gin[((long)(t0 * 256 + b0 + pb)) * NPAD + dir * 400 + hid];
        g0 = gp[0]; g1 = gp[100]; g2 = gp[200]; g3 = gp[300];
    }
    __syncthreads();

    for (int step = 0; step < TT; ++step) {
        const int t = dir ? (TT - 1 - step) : step;

        // ---- phase 1: per-batch quarter matvec for 4 gate rows ----
#pragma unroll
        for (int b = 0; b < 4; b++) {
            const float* hb = &hs[b * 116 + q * 28];
            ULL a0 = 0ull, a1 = 0ull, a2 = 0ull, a3 = 0ull;
#pragma unroll
            for (int m = 0; m < 6; m++) {
                ulonglong2 hp = *(const ulonglong2*)(hb + 4 * m);
                ffma2(a0, w[0][2 * m], hp.x); ffma2(a0, w[0][2 * m + 1], hp.y);
                ffma2(a1, w[1][2 * m], hp.x); ffma2(a1, w[1][2 * m + 1], hp.y);
                ffma2(a2, w[2][2 * m], hp.x); ffma2(a2, w[2][2 * m + 1], hp.y);
                ffma2(a3, w[3][2 * m], hp.x); ffma2(a3, w[3][2 * m + 1], hp.y);
            }
            {
                ULL ht = *(const ULL*)(hb + 24);   // (h24, 0)
                ffma2(a0, w[0][12], ht); ffma2(a1, w[1][12], ht);
                ffma2(a2, w[2][12], ht); ffma2(a3, w[3][12], ht);
            }
            float2 f0 = unpack2(a0), f1 = unpack2(a1), f2 = unpack2(a2), f3 = unpack2(a3);
            float* pr = &psh[(q * 4 + b) * 400 + hid];
            pr[0]   = f0.x + f0.y;
            pr[100] = f1.x + f1.y;
            pr[200] = f2.x + f2.y;
            pr[300] = f3.x + f3.y;
        }
        __syncthreads();

        // ---- phase 2: 4-way reduce + gate finalize + cell update ----
        {
            const float* p0 = &psh[(0 * 4 + pb) * 400 + hid];
            const float* p1 = &psh[(1 * 4 + pb) * 400 + hid];
            const float* p2 = &psh[(2 * 4 + pb) * 400 + hid];
            const float* p3 = &psh[(3 * 4 + pb) * 400 + hid];
            float pi = g0 + p0[0]   + p1[0]   + p2[0]   + p3[0];
            float pf = g1 + p0[100] + p1[100] + p2[100] + p3[100];
            float pg = g2 + p0[200] + p1[200] + p2[200] + p3[200];
            float po = g3 + p0[300] + p1[300] + p2[300] + p3[300];
            c = sigf(pf) * c + sigf(pi) * tanhf_fast(pg);
            float h = sigf(po) * tanhf_fast(c);
            hs[pb * 116 + hq * 28 + hr] = h;
            d_h2T[(long)(dir * 100 + hid) * MROWS + (b0 + pb) * TT + t] = pack2(h, h);

            // prefetch next step's gin
            int sn = (step + 1 < TT) ? (step + 1) : step;
            int tn = dir ? (TT - 1 - sn) : sn;
            const float* gp = &d_gin[((long)(tn * 256 + b0 + pb)) * NPAD + dir * 400 + hid];
            g0 = gp[0]; g1 = gp[100]; g2 = gp[200]; g3 = gp[300];
        }
        __syncthreads();
    }
}

// ---------------- combine: gather + tanh + (300->3) + softmax --------------------
__global__ __launch_bounds__(256) void combine_k(const int* __restrict__ paths,
                                                 const float* __restrict__ b1,
                                                 const float* __restrict__ W2,
                                                 const float* __restrict__ b2,
                                                 float* __restrict__ out) {
    const int warp = (blockIdx.x * blockDim.x + threadIdx.x) >> 5;
    const int lane = threadIdx.x & 31;
    if (warp >= BB * CC) return;
    const int b = warp / CC;

    const int* p = &paths[warp * 3];
    int p0 = __ldg(p), p1 = __ldg(p + 1), p2 = __ldg(p + 2);
    int i0 = min(max(p0, 0), TT - 1);
    int i1 = min(max(p1, 0), TT - 1);
    int i2 = min(max(p2, 0), TT - 1);

    const float* S0 = &d_S[(long)(b * TT + i0) * NPAD];
    const float* S1 = &d_S[(long)(b * TT + i1) * NPAD + 300];
    const float* S2 = &d_S[(long)(b * TT + i2) * NPAD + 600];

    float z0 = 0.f, z1 = 0.f, z2 = 0.f;
    for (int m = lane; m < MLPD; m += 32) {
        float hv = __ldg(&b1[m]);
        if (p0 >= 0) hv += S0[m];
        if (p1 >= 0) hv += S1[m];
        if (p2 >= 0) hv += S2[m];
        hv = tanhf_fast(hv);
        z0 = fmaf(hv, __ldg(&W2[m * 3 + 0]), z0);
        z1 = fmaf(hv, __ldg(&W2[m * 3 + 1]), z1);
        z2 = fmaf(hv, __ldg(&W2[m * 3 + 2]), z2);
    }
#pragma unroll
    for (int off = 16; off; off >>= 1) {
        z0 += __shfl_xor_sync(0xFFFFFFFFu, z0, off);
        z1 += __shfl_xor_sync(0xFFFFFFFFu, z1, off);
        z2 += __shfl_xor_sync(0xFFFFFFFFu, z2, off);
    }
    if (lane == 0) {
        z0 += __ldg(&b2[0]); z1 += __ldg(&b2[1]); z2 += __ldg(&b2[2]);
        float mx = fmaxf(z0, fmaxf(z1, z2));
        float e0 = __expf(z0 - mx), e1 = __expf(z1 - mx), e2 = __expf(z2 - mx);
        float inv = 1.0f / (e0 + e1 + e2);
        out[warp * 3 + 0] = e0 * inv;
        out[warp * 3 + 1] = e1 * inv;
        out[warp * 3 + 2] = e2 * inv;
    }
}

// -------------------------------- launch -----------------------------------------
extern "C" void kernel_launch(void* const* d_in, const int* in_sizes, int n_in,
                              void* d_out, int out_size) {
    const int*   x     = (const int*)  d_in[0];
    const int*   paths = (const int*)  d_in[1];
    const float* emb   = (const float*)d_in[2];
    const float* Whh_f = (const float*)d_in[4];
    const float* Whh_b = (const float*)d_in[8];
    const float* W1    = (const float*)d_in[11];
    const float* b1    = (const float*)d_in[12];
    const float* W2    = (const float*)d_in[13];
    const float* b2    = (const float*)d_in[14];
    float* out = (float*)d_out;

    prep_k<<<128, 256>>>((const float*)d_in[3], (const float*)d_in[7],
                         (const float*)d_in[5], (const float*)d_in[6],
                         (const float*)d_in[9], (const float*)d_in[10], W1);

    xet_k<<<256, 512>>>(x, emb);

    { dim3 g(256, 7); gates_gemm_k<<<g, 512>>>(); }   // 800 cols, last tile overlapped

    lstm_k<<<128, 400>>>(Whh_f, Whh_b);

    { dim3 g(256, 8); s_gemm_k<<<g, 512>>>(); }       // 900 cols, last tile overlapped

    {
        int warps = BB * CC;
        int blocks = (warps * 32 + 255) / 256;
        combine_k<<<blocks, 256>>>(paths, b1, W2, b2, out);
    }
}

// round 6
// speedup vs baseline: 1.1017x; 1.0008x over previous
#include <cuda_runtime.h>
#include <math.h>

#define BB   256
#define TT   128
#define EE   100
#define HH   100
#define CC   255
#define MLPD 300
#define MROWS 32768        // B*T
#define NPAD 1024

typedef unsigned long long ULL;

__device__ __forceinline__ void ffma2(ULL& acc, ULL a, ULL b) {
    asm volatile("fma.rn.f32x2 %0, %1, %2, %0;" : "+l"(acc) : "l"(a), "l"(b));
}
__device__ __forceinline__ ULL pack2(float x, float y) {
    ULL r; asm("mov.b64 %0, {%1,%2};" : "=l"(r) : "f"(x), "f"(y)); return r;
}
__device__ __forceinline__ float2 unpack2(ULL v) {
    float2 r; asm("mov.b64 {%0,%1}, %2;" : "=f"(r.x), "=f"(r.y) : "l"(v)); return r;
}
__device__ __forceinline__ float tanhf_fast(float x) {
    float r; asm("tanh.approx.f32 %0, %1;" : "=f"(r) : "f"(x)); return r;
}
__device__ __forceinline__ float sigf(float x) { return 0.5f * tanhf_fast(0.5f * x) + 0.5f; }

// ---------------- device-global scratch ----------------------------------------
__device__ ULL   d_xeT[100 * MROWS];        // dup pairs, [k][r], r=t*256+b
__device__ float d_WtIn[100 * NPAD];        // [k][col] col<800 valid (400 fwd | 400 bwd)
__device__ float d_bsum[NPAD];
__device__ float d_gin[MROWS * NPAD];       // [r=t*256+b][col] col = dir*400 + gate*100 + hid
__device__ ULL   d_h2T[200 * MROWS];        // dup pairs, [k=dir*100+hid][r=b*128+t]
__device__ float d_WtS[200 * NPAD];         // [k][s*300+m], cols>=900 zero
__device__ float d_S[MROWS * NPAD];         // [r=b*128+t][col]

// ---------------- prep ----------------------------------------------------------
__global__ void prep_k(const float* __restrict__ Wih_f, const float* __restrict__ Wih_b,
                       const float* __restrict__ bih_f, const float* __restrict__ bhh_f,
                       const float* __restrict__ bih_b, const float* __restrict__ bhh_b,
                       const float* __restrict__ W1) {
    int stride = gridDim.x * blockDim.x;
    int i0 = blockIdx.x * blockDim.x + threadIdx.x;
    for (int idx = i0; idx < 100 * NPAD; idx += stride) {
        int k = idx / NPAD, col = idx % NPAD;
        float v = 0.0f;
        if (col < 400)      v = Wih_f[col * 100 + k];
        else if (col < 800) v = Wih_b[(col - 400) * 100 + k];
        d_WtIn[idx] = v;
    }
    for (int idx = i0; idx < NPAD; idx += stride) {
        float v = 0.0f;
        if (idx < 400)      v = bih_f[idx] + bhh_f[idx];
        else if (idx < 800) v = bih_b[idx - 400] + bhh_b[idx - 400];
        d_bsum[idx] = v;
    }
    for (int idx = i0; idx < 200 * NPAD; idx += stride) {
        int k = idx / NPAD, col = idx % NPAD;
        float v = 0.0f;
        if (col < 900) {
            int s = col / MLPD, m = col % MLPD;
            v = W1[(s * 200 + k) * MLPD + m];
        }
        d_WtS[idx] = v;
    }
}

// ---------------- embed gather + transpose + duplicate --------------------------
__global__ __launch_bounds__(512) void xet_k(const int* __restrict__ x,
                                             const float* __restrict__ emb) {
    __shared__ float sh[128][101];
    __shared__ int toks[128];
    const int tid = threadIdx.x;
    const int r0 = blockIdx.x * 128;
    if (tid < 128) {
        int r = r0 + tid;
        toks[tid] = x[(r & 255) * TT + (r >> 8)];   // r = t*256+b
    }
    __syncthreads();
    for (int idx = tid; idx < 128 * 100; idx += 512) {
        int row = idx / 100, k = idx % 100;
        sh[row][k] = emb[(long)toks[row] * EE + k];
    }
    __syncthreads();
    for (int idx = tid; idx < 100 * 128; idx += 512) {
        int k = idx >> 7, j = idx & 127;
        float v = sh[j][k];
        d_xeT[(long)k * MROWS + r0 + j] = pack2(v, v);
    }
}

// ---------------- GEMM: C[M, cols of NC] = A_dup^T @ B (+bias) ------------------
template <int KT, bool BIAS>
__device__ __forceinline__ void gemm_body(const ULL* __restrict__ Adup,
                                          const float* __restrict__ Bw,
                                          const float* __restrict__ bias,
                                          float* __restrict__ Cout, int NC) {
    __shared__ __align__(16) ULL   As[20][128];
    __shared__ __align__(16) float Bs[20][128];
    const int tid = threadIdx.x;
    const int tx = tid & 31;
    const int ty = tid >> 5;
    const int r0 = blockIdx.x * 128;
    const int c0 = min((int)blockIdx.y * 128, NC - 128);

    ULL acc[8][2];
    if (BIAS) {
        ulonglong2 bp = *(const ulonglong2*)&bias[c0 + tx * 4];
#pragma unroll
        for (int i = 0; i < 8; i++) { acc[i][0] = bp.x; acc[i][1] = bp.y; }
    } else {
#pragma unroll
        for (int i = 0; i < 8; i++) { acc[i][0] = 0ull; acc[i][1] = 0ull; }
    }

    ULL apf[5]; float bpf[5];
#pragma unroll
    for (int j = 0; j < 5; j++) {
        int idx = tid + 512 * j;
        int kk = idx >> 7, rr = idx & 127;
        apf[j] = Adup[(long)kk * MROWS + r0 + rr];
        bpf[j] = Bw[kk * NPAD + c0 + rr];
    }

    for (int kt = 0; kt < KT; kt++) {
#pragma unroll
        for (int j = 0; j < 5; j++) {
            int idx = tid + 512 * j;
            int kk = idx >> 7, rr = idx & 127;
            As[kk][rr] = apf[j];
            Bs[kk][rr] = bpf[j];
        }
        __syncthreads();
        if (kt + 1 < KT) {
            int kbase = (kt + 1) * 20;
#pragma unroll
            for (int j = 0; j < 5; j++) {
                int idx = tid + 512 * j;
                int kk = idx >> 7, rr = idx & 127;
                apf[j] = Adup[(long)(kbase + kk) * MROWS + r0 + rr];
                bpf[j] = Bw[(kbase + kk) * NPAD + c0 + rr];
            }
        }
#pragma unroll
        for (int kk = 0; kk < 20; kk++) {
            ulonglong2 bp = *(const ulonglong2*)&Bs[kk][tx * 4];
#pragma unroll
            for (int i2 = 0; i2 < 4; i2++) {
                ulonglong2 a2 = *(const ulonglong2*)&As[kk][ty * 8 + i2 * 2];
                ffma2(acc[i2 * 2][0],     a2.x, bp.x);
                ffma2(acc[i2 * 2][1],     a2.x, bp.y);
                ffma2(acc[i2 * 2 + 1][0], a2.y, bp.x);
                ffma2(acc[i2 * 2 + 1][1], a2.y, bp.y);
            }
        }
        __syncthreads();
    }
#pragma unroll
    for (int i = 0; i < 8; i++) {
        float2 v0 = unpack2(acc[i][0]);
        float2 v1 = unpack2(acc[i][1]);
        *(float4*)&Cout[(long)(r0 + ty * 8 + i) * NPAD + c0 + tx * 4] =
            make_float4(v0.x, v0.y, v1.x, v1.y);
    }
}

__global__ __launch_bounds__(512) void gates_gemm_k() {
    gemm_body<5, true>(d_xeT, d_WtIn, d_bsum, d_gin, 800);
}
__global__ __launch_bounds__(512) void s_gemm_k() {
    gemm_body<10, false>(d_h2T, d_WtS, nullptr, d_S, 900);
}

// ---------------- LSTM recurrence: shuffle-reduced, 1 barrier/step ---------------
// 128 blocks: dir = blk>>6, batch base = (blk&63)*4. 400 threads:
//   tid = hid*4 + q  (hid 0..99, q 0..3 = k-quarter AND batch for cell update).
//   Phase 1: thread computes partials for all 4 batches x 4 gates over its
//   k-quarter; weights 4x13 ULL in regs. Lane layout puts the 4 q's of one hid
//   in adjacent lanes -> 2-stage shfl_xor allreduce replaces smem reduction.
//   Phase 2 (in-thread): batch q cell update. Double-buffered h, 1 barrier/step.
__global__ __launch_bounds__(400, 1) void lstm_k(const float* __restrict__ Whh_f,
                                                 const float* __restrict__ Whh_b) {
    __shared__ __align__(16) float hs[2][4 * 116];   // [buf][b*116 + hq*28 + i]
    const int tid = threadIdx.x;
    const int dir = blockIdx.x >> 6;
    const int b0 = (blockIdx.x & 63) * 4;
    const float* __restrict__ Whh = dir ? Whh_b : Whh_f;

    const int hid = tid >> 2;
    const int q = tid & 3;

    // Pack weights: w[g][p] over k in [q*25, q*25+25): pairs (2p,2p+1), p12=(k24,0)
    ULL w[4][13];
#pragma unroll
    for (int g = 0; g < 4; g++) {
        const float* row = Whh + (g * 100 + hid) * 100 + q * 25;
#pragma unroll
        for (int p = 0; p < 12; p++) w[g][p] = pack2(row[2 * p], row[2 * p + 1]);
        w[g][12] = pack2(row[24], 0.0f);
    }
    for (int idx = tid; idx < 2 * 4 * 116; idx += 400) hs[0][idx] = 0.0f;

    const int hq = hid / 25, hr = hid % 25;          // h store slot for batch q
    float c = 0.0f;
    float g0, g1, g2, g3;
    {
        int t0 = dir ? (TT - 1) : 0;
        const float* gp = &d_gin[((long)(t0 * 256 + b0 + q)) * NPAD + dir * 400 + hid];
        g0 = gp[0]; g1 = gp[100]; g2 = gp[200]; g3 = gp[300];
    }
    __syncthreads();

    for (int step = 0; step < TT; ++step) {
        const int t = dir ? (TT - 1 - step) : step;
        const float* hbuf = hs[step & 1];
        float* hnxt = hs[(step + 1) & 1];

        // ---- phase 1: per-batch quarter matvec for 4 gate rows ----
        float v[4][4];
#pragma unroll
        for (int b = 0; b < 4; b++) {
            const float* hb = &hbuf[b * 116 + q * 28];
            ULL a0 = 0ull, a1 = 0ull, a2 = 0ull, a3 = 0ull;
#pragma unroll
            for (int m = 0; m < 6; m++) {
                ulonglong2 hp = *(const ulonglong2*)(hb + 4 * m);
                ffma2(a0, w[0][2 * m], hp.x); ffma2(a0, w[0][2 * m + 1], hp.y);
                ffma2(a1, w[1][2 * m], hp.x); ffma2(a1, w[1][2 * m + 1], hp.y);
                ffma2(a2, w[2][2 * m], hp.x); ffma2(a2, w[2][2 * m + 1], hp.y);
                ffma2(a3, w[3][2 * m], hp.x); ffma2(a3, w[3][2 * m + 1], hp.y);
            }
            {
                ULL ht = *(const ULL*)(hb + 24);   // (h24, 0)
                ffma2(a0, w[0][12], ht); ffma2(a1, w[1][12], ht);
                ffma2(a2, w[2][12], ht); ffma2(a3, w[3][12], ht);
            }
            float2 f0 = unpack2(a0), f1 = unpack2(a1), f2 = unpack2(a2), f3 = unpack2(a3);
            v[b][0] = f0.x + f0.y;
            v[b][1] = f1.x + f1.y;
            v[b][2] = f2.x + f2.y;
            v[b][3] = f3.x + f3.y;
        }

        // ---- allreduce over the 4 k-quarters (adjacent lanes) ----
#pragma unroll
        for (int b = 0; b < 4; b++)
#pragma unroll
            for (int g = 0; g < 4; g++)
                v[b][g] += __shfl_xor_sync(0xFFFFFFFFu, v[b][g], 1);
#pragma unroll
        for (int b = 0; b < 4; b++)
#pragma unroll
            for (int g = 0; g < 4; g++)
                v[b][g] += __shfl_xor_sync(0xFFFFFFFFu, v[b][g], 2);

        // ---- phase 2 (in-thread): batch q cell update ----
        {
            float pi = g0 + v[q][0];
            float pf = g1 + v[q][1];
            float pg = g2 + v[q][2];
            float po = g3 + v[q][3];
            c = sigf(pf) * c + sigf(pi) * tanhf_fast(pg);
            float h = sigf(po) * tanhf_fast(c);
            hnxt[q * 116 + hq * 28 + hr] = h;
            d_h2T[(long)(dir * 100 + hid) * MROWS + (b0 + q) * TT + t] = pack2(h, h);

            // prefetch next step's gin
            int sn = (step + 1 < TT) ? (step + 1) : step;
            int tn = dir ? (TT - 1 - sn) : sn;
            const float* gp = &d_gin[((long)(tn * 256 + b0 + q)) * NPAD + dir * 400 + hid];
            g0 = gp[0]; g1 = gp[100]; g2 = gp[200]; g3 = gp[300];
        }
        __syncthreads();
    }
}

// ---------------- combine: gather + tanh + (300->3) + softmax --------------------
__global__ __launch_bounds__(256) void combine_k(const int* __restrict__ paths,
                                                 const float* __restrict__ b1,
                                                 const float* __restrict__ W2,
                                                 const float* __restrict__ b2,
                                                 float* __restrict__ out) {
    const int warp = (blockIdx.x * blockDim.x + threadIdx.x) >> 5;
    const int lane = threadIdx.x & 31;
    if (warp >= BB * CC) return;
    const int b = warp / CC;

    const int* p = &paths[warp * 3];
    int p0 = __ldg(p), p1 = __ldg(p + 1), p2 = __ldg(p + 2);
    int i0 = min(max(p0, 0), TT - 1);
    int i1 = min(max(p1, 0), TT - 1);
    int i2 = min(max(p2, 0), TT - 1);

    const float* S0 = &d_S[(long)(b * TT + i0) * NPAD];
    const float* S1 = &d_S[(long)(b * TT + i1) * NPAD + 300];
    const float* S2 = &d_S[(long)(b * TT + i2) * NPAD + 600];

    float z0 = 0.f, z1 = 0.f, z2 = 0.f;
    for (int m = lane; m < MLPD; m += 32) {
        float hv = __ldg(&b1[m]);
        if (p0 >= 0) hv += S0[m];
        if (p1 >= 0) hv += S1[m];
        if (p2 >= 0) hv += S2[m];
        hv = tanhf_fast(hv);
        z0 = fmaf(hv, __ldg(&W2[m * 3 + 0]), z0);
        z1 = fmaf(hv, __ldg(&W2[m * 3 + 1]), z1);
        z2 = fmaf(hv, __ldg(&W2[m * 3 + 2]), z2);
    }
#pragma unroll
    for (int off = 16; off; off >>= 1) {
        z0 += __shfl_xor_sync(0xFFFFFFFFu, z0, off);
        z1 += __shfl_xor_sync(0xFFFFFFFFu, z1, off);
        z2 += __shfl_xor_sync(0xFFFFFFFFu, z2, off);
    }
    if (lane == 0) {
        z0 += __ldg(&b2[0]); z1 += __ldg(&b2[1]); z2 += __ldg(&b2[2]);
        float mx = fmaxf(z0, fmaxf(z1, z2));
        float e0 = __expf(z0 - mx), e1 = __expf(z1 - mx), e2 = __expf(z2 - mx);
        float inv = 1.0f / (e0 + e1 + e2);
        out[warp * 3 + 0] = e0 * inv;
        out[warp * 3 + 1] = e1 * inv;
        out[warp * 3 + 2] = e2 * inv;
    }
}

// -------------------------------- launch -----------------------------------------
extern "C" void kernel_launch(void* const* d_in, const int* in_sizes, int n_in,
                              void* d_out, int out_size) {
    const int*   x     = (const int*)  d_in[0];
    const int*   paths = (const int*)  d_in[1];
    const float* emb   = (const float*)d_in[2];
    const float* Whh_f = (const float*)d_in[4];
    const float* Whh_b = (const float*)d_in[8];
    const float* W1    = (const float*)d_in[11];
    const float* b1    = (const float*)d_in[12];
    const float* W2    = (const float*)d_in[13];
    const float* b2    = (const float*)d_in[14];
    float* out = (float*)d_out;

    prep_k<<<128, 256>>>((const float*)d_in[3], (const float*)d_in[7],
                         (const float*)d_in[5], (const float*)d_in[6],
                         (const float*)d_in[9], (const float*)d_in[10], W1);

    xet_k<<<256, 512>>>(x, emb);

    { dim3 g(256, 7); gates_gemm_k<<<g, 512>>>(); }   // 800 cols, last tile overlapped

    lstm_k<<<128, 400>>>(Whh_f, Whh_b);

    { dim3 g(256, 8); s_gemm_k<<<g, 512>>>(); }       // 900 cols, last tile overlapped

    {
        int warps = BB * CC;
        int blocks = (warps * 32 + 255) / 256;
        combine_k<<<blocks, 256>>>(paths, b1, W2, b2, out);
    }
}

// round 7
// speedup vs baseline: 1.1085x; 1.0062x over previous
#include <cuda_runtime.h>
#include <math.h>

#define BB   256
#define TT   128
#define EE   100
#define HH   100
#define CC   255
#define MLPD 300
#define MROWS 32768        // B*T
#define NPAD 1024

typedef unsigned long long ULL;

__device__ __forceinline__ void ffma2(ULL& acc, ULL a, ULL b) {
    asm volatile("fma.rn.f32x2 %0, %1, %2, %0;" : "+l"(acc) : "l"(a), "l"(b));
}
__device__ __forceinline__ ULL pack2(float x, float y) {
    ULL r; asm("mov.b64 %0, {%1,%2};" : "=l"(r) : "f"(x), "f"(y)); return r;
}
__device__ __forceinline__ float2 unpack2(ULL v) {
    float2 r; asm("mov.b64 {%0,%1}, %2;" : "=f"(r.x), "=f"(r.y) : "l"(v)); return r;
}
__device__ __forceinline__ float tanhf_fast(float x) {
    float r; asm("tanh.approx.f32 %0, %1;" : "=f"(r) : "f"(x)); return r;
}
__device__ __forceinline__ float sigf(float x) { return 0.5f * tanhf_fast(0.5f * x) + 0.5f; }

// ---------------- device-global scratch ----------------------------------------
__device__ ULL   d_xeT[100 * MROWS];        // dup pairs, [k][r], r=t*256+b
__device__ float d_WtIn[100 * NPAD];        // [k][col] col<800 valid (400 fwd | 400 bwd)
__device__ float d_bsum[NPAD];
__device__ float d_gin[MROWS * NPAD];       // [r=t*256+b][col] col = dir*400 + gate*100 + hid
__device__ ULL   d_h2T[200 * MROWS];        // dup pairs, [k=dir*100+hid][r=b*128+t]
__device__ float d_WtS[200 * NPAD];         // [k][s*300+m], cols>=900 zero
__device__ float d_S[MROWS * NPAD];         // [r=b*128+t][col]

// ---------------- prep ----------------------------------------------------------
__global__ void prep_k(const float* __restrict__ Wih_f, const float* __restrict__ Wih_b,
                       const float* __restrict__ bih_f, const float* __restrict__ bhh_f,
                       const float* __restrict__ bih_b, const float* __restrict__ bhh_b,
                       const float* __restrict__ W1) {
    int stride = gridDim.x * blockDim.x;
    int i0 = blockIdx.x * blockDim.x + threadIdx.x;
    for (int idx = i0; idx < 100 * NPAD; idx += stride) {
        int k = idx / NPAD, col = idx % NPAD;
        float v = 0.0f;
        if (col < 400)      v = Wih_f[col * 100 + k];
        else if (col < 800) v = Wih_b[(col - 400) * 100 + k];
        d_WtIn[idx] = v;
    }
    for (int idx = i0; idx < NPAD; idx += stride) {
        float v = 0.0f;
        if (idx < 400)      v = bih_f[idx] + bhh_f[idx];
        else if (idx < 800) v = bih_b[idx - 400] + bhh_b[idx - 400];
        d_bsum[idx] = v;
    }
    for (int idx = i0; idx < 200 * NPAD; idx += stride) {
        int k = idx / NPAD, col = idx % NPAD;
        float v = 0.0f;
        if (col < 900) {
            int s = col / MLPD, m = col % MLPD;
            v = W1[(s * 200 + k) * MLPD + m];
        }
        d_WtS[idx] = v;
    }
}

// ---------------- embed gather + transpose + duplicate --------------------------
__global__ __launch_bounds__(512) void xet_k(const int* __restrict__ x,
                                             const float* __restrict__ emb) {
    __shared__ float sh[128][101];
    __shared__ int toks[128];
    const int tid = threadIdx.x;
    const int r0 = blockIdx.x * 128;
    if (tid < 128) {
        int r = r0 + tid;
        toks[tid] = x[(r & 255) * TT + (r >> 8)];   // r = t*256+b
    }
    __syncthreads();
    for (int idx = tid; idx < 128 * 100; idx += 512) {
        int row = idx / 100, k = idx % 100;
        sh[row][k] = emb[(long)toks[row] * EE + k];
    }
    __syncthreads();
    for (int idx = tid; idx < 100 * 128; idx += 512) {
        int k = idx >> 7, j = idx & 127;
        float v = sh[j][k];
        d_xeT[(long)k * MROWS + r0 + j] = pack2(v, v);
    }
}

// ---------------- GEMM: C[M, cols of NC] = A_dup^T @ B (+bias) ------------------
// BM=128, BN=128, BK=20, 512 threads, TM=8, TN=4, f32x2.
// Double-buffered smem, single __syncthreads per k-tile.
template <int KT, bool BIAS>
__device__ __forceinline__ void gemm_body(const ULL* __restrict__ Adup,
                                          const float* __restrict__ Bw,
                                          const float* __restrict__ bias,
                                          float* __restrict__ Cout, int NC) {
    extern __shared__ char smx[];
    ULL*   As = (ULL*)smx;                         // [2][20][128]
    float* Bs = (float*)(smx + 2 * 20 * 128 * 8);  // [2][20][128]
    const int tid = threadIdx.x;
    const int tx = tid & 31;
    const int ty = tid >> 5;
    const int r0 = blockIdx.x * 128;
    const int c0 = min((int)blockIdx.y * 128, NC - 128);

    ULL acc[8][2];
    if (BIAS) {
        ulonglong2 bp = *(const ulonglong2*)&bias[c0 + tx * 4];
#pragma unroll
        for (int i = 0; i < 8; i++) { acc[i][0] = bp.x; acc[i][1] = bp.y; }
    } else {
#pragma unroll
        for (int i = 0; i < 8; i++) { acc[i][0] = 0ull; acc[i][1] = 0ull; }
    }

    ULL apf[5]; float bpf[5];
#pragma unroll
    for (int j = 0; j < 5; j++) {
        int idx = tid + 512 * j;
        int kk = idx >> 7, rr = idx & 127;
        apf[j] = Adup[(long)kk * MROWS + r0 + rr];
        bpf[j] = Bw[kk * NPAD + c0 + rr];
    }
#pragma unroll
    for (int j = 0; j < 5; j++) {
        int idx = tid + 512 * j;
        As[idx] = apf[j];
        Bs[idx] = bpf[j];
    }
    __syncthreads();

    for (int kt = 0; kt < KT; kt++) {
        const int p = kt & 1;
        if (kt + 1 < KT) {
            int kbase = (kt + 1) * 20;
#pragma unroll
            for (int j = 0; j < 5; j++) {
                int idx = tid + 512 * j;
                int kk = idx >> 7, rr = idx & 127;
                apf[j] = Adup[(long)(kbase + kk) * MROWS + r0 + rr];
                bpf[j] = Bw[(kbase + kk) * NPAD + c0 + rr];
            }
        }
        const ULL*   Ap = As + p * 2560;
        const float* Bp = Bs + p * 2560;
#pragma unroll
        for (int kk = 0; kk < 20; kk++) {
            ulonglong2 bp = *(const ulonglong2*)&Bp[kk * 128 + tx * 4];
#pragma unroll
            for (int i2 = 0; i2 < 4; i2++) {
                ulonglong2 a2 = *(const ulonglong2*)&Ap[kk * 128 + ty * 8 + i2 * 2];
                ffma2(acc[i2 * 2][0],     a2.x, bp.x);
                ffma2(acc[i2 * 2][1],     a2.x, bp.y);
                ffma2(acc[i2 * 2 + 1][0], a2.y, bp.x);
                ffma2(acc[i2 * 2 + 1][1], a2.y, bp.y);
            }
        }
        if (kt + 1 < KT) {
            ULL*   An = As + (p ^ 1) * 2560;
            float* Bn = Bs + (p ^ 1) * 2560;
#pragma unroll
            for (int j = 0; j < 5; j++) {
                int idx = tid + 512 * j;
                An[idx] = apf[j];
                Bn[idx] = bpf[j];
            }
        }
        __syncthreads();
    }
#pragma unroll
    for (int i = 0; i < 8; i++) {
        float2 v0 = unpack2(acc[i][0]);
        float2 v1 = unpack2(acc[i][1]);
        *(float4*)&Cout[(long)(r0 + ty * 8 + i) * NPAD + c0 + tx * 4] =
            make_float4(v0.x, v0.y, v1.x, v1.y);
    }
}

__global__ __launch_bounds__(512) void gates_gemm_k() {
    gemm_body<5, true>(d_xeT, d_WtIn, d_bsum, d_gin, 800);
}
__global__ __launch_bounds__(512) void s_gemm_k() {
    gemm_body<10, false>(d_h2T, d_WtS, nullptr, d_S, 900);
}

#define GEMM_SMEM (2 * 20 * 128 * 8 + 2 * 20 * 128 * 4)

// ---------------- LSTM recurrence: 800 thr, 2 gates/thread, shuffle scatter ------
// 128 blocks: dir = blk>>6, batch base = (blk&63)*4.
// tid = hid*8 + q*2 + gh: hid 0..99, q = k-quarter AND batch owner, gh = gate pair
// (gh0 -> gates i,f; gh1 -> g,o). Weights 2x13 ULL = 52 regs -> no spill at 25 warps.
// Reduce: 4 SHFL (q bit1) + 2 SHFL (q bit0) + 2 SHFL (gate exchange) = 8/step.
// Both gh lanes compute identical (c,h); gh0 writes. 1 barrier/step, dbl-buffered h.
__global__ __launch_bounds__(800, 1) void lstm_k(const float* __restrict__ Whh_f,
                                                 const float* __restrict__ Whh_b) {
    __shared__ __align__(16) float hs[2][4 * 116];   // [buf][b*116 + hq*28 + i]
    const int tid = threadIdx.x;
    const int dir = blockIdx.x >> 6;
    const int b0 = (blockIdx.x & 63) * 4;
    const float* __restrict__ Whh = dir ? Whh_b : Whh_f;

    const int hid = tid >> 3;
    const int sub = tid & 7;
    const int q = sub >> 1;          // lane bits [1:2]
    const int gh = sub & 1;          // lane bit 0
    const int hi2 = (q >> 1) & 1;
    const int lo = q & 1;

    // Weights for gates gh*2, gh*2+1 over k in [q*25, q*25+25)
    ULL w[2][13];
#pragma unroll
    for (int g2 = 0; g2 < 2; g2++) {
        const float* row = Whh + ((gh * 2 + g2) * 100 + hid) * 100 + q * 25;
#pragma unroll
        for (int p = 0; p < 12; p++) w[g2][p] = pack2(row[2 * p], row[2 * p + 1]);
        w[g2][12] = pack2(row[24], 0.0f);
    }
    for (int idx = tid; idx < 2 * 4 * 116; idx += 800) hs[0][idx] = 0.0f;

    const int hq = hid / 25, hr = hid % 25;          // h store slot (batch q, gh0)
    float c = 0.0f;
    float g0, g1;
    {
        int t0 = dir ? (TT - 1) : 0;
        const float* gp = &d_gin[((long)(t0 * 256 + b0 + q)) * NPAD + dir * 400 + gh * 200 + hid];
        g0 = gp[0]; g1 = gp[100];
    }
    __syncthreads();

    for (int step = 0; step < TT; ++step) {
        const int t = dir ? (TT - 1 - step) : step;
        const float* hbuf = hs[step & 1];
        float* hnxt = hs[(step + 1) & 1];

        // ---- quarter matvec for 2 gate rows x 4 batches ----
        float v[4][2];
#pragma unroll
        for (int b = 0; b < 4; b++) {
            const float* hb = &hbuf[b * 116 + q * 28];
            ULL a0 = 0ull, a1 = 0ull;
#pragma unroll
            for (int m = 0; m < 6; m++) {
                ulonglong2 hp = *(const ulonglong2*)(hb + 4 * m);
                ffma2(a0, w[0][2 * m], hp.x); ffma2(a0, w[0][2 * m + 1], hp.y);
                ffma2(a1, w[1][2 * m], hp.x); ffma2(a1, w[1][2 * m + 1], hp.y);
            }
            {
                ULL ht = *(const ULL*)(hb + 24);   // (h24, pad0)
                ffma2(a0, w[0][12], ht); ffma2(a1, w[1][12], ht);
            }
            float2 f0 = unpack2(a0), f1 = unpack2(a1);
            v[b][0] = f0.x + f0.y;
            v[b][1] = f1.x + f1.y;
        }

        // ---- reduce-scatter over quarters ----
        // stage A (xor 4 = q bit1): keep batches with bit1(b)==hi2
        float u[2][2];
#pragma unroll
        for (int j = 0; j < 2; j++)
#pragma unroll
            for (int g = 0; g < 2; g++) {
                float keep = hi2 ? v[2 + j][g] : v[j][g];
                float send = hi2 ? v[j][g]     : v[2 + j][g];
                u[j][g] = keep + __shfl_xor_sync(0xFFFFFFFFu, send, 4);
            }
        // stage B (xor 2 = q bit0): keep j==lo  -> sums for batch q
        float s0, s1;
        {
            float k0 = lo ? u[1][0] : u[0][0];
            float e0 = lo ? u[0][0] : u[1][0];
            s0 = k0 + __shfl_xor_sync(0xFFFFFFFFu, e0, 2);
            float k1 = lo ? u[1][1] : u[0][1];
            float e1 = lo ? u[0][1] : u[1][1];
            s1 = k1 + __shfl_xor_sync(0xFFFFFFFFu, e1, 2);
        }

        // ---- gate-pair exchange (xor 1) + cell update (both lanes identical) ----
        float uA = g0 + s0;
        float uB = g1 + s1;
        float oA = __shfl_xor_sync(0xFFFFFFFFu, uA, 1);
        float oB = __shfl_xor_sync(0xFFFFFFFFu, uB, 1);
        float pi = gh ? oA : uA;
        float pf = gh ? oB : uB;
        float pg = gh ? uA : oA;
        float po = gh ? uB : oB;
        c = sigf(pf) * c + sigf(pi) * tanhf_fast(pg);
        float h = sigf(po) * tanhf_fast(c);
        if (gh == 0) {
            hnxt[q * 116 + hq * 28 + hr] = h;
            d_h2T[(long)(dir * 100 + hid) * MROWS + (b0 + q) * TT + t] = pack2(h, h);
        }

        // prefetch next step's gin
        {
            int sn = (step + 1 < TT) ? (step + 1) : step;
            int tn = dir ? (TT - 1 - sn) : sn;
            const float* gp = &d_gin[((long)(tn * 256 + b0 + q)) * NPAD + dir * 400 + gh * 200 + hid];
            g0 = gp[0]; g1 = gp[100];
        }
        __syncthreads();
    }
}

// ---------------- combine: gather + tanh + (300->3) + softmax --------------------
__global__ __launch_bounds__(256) void combine_k(const int* __restrict__ paths,
                                                 const float* __restrict__ b1,
                                                 const float* __restrict__ W2,
                                                 const float* __restrict__ b2,
                                                 float* __restrict__ out) {
    const int warp = (blockIdx.x * blockDim.x + threadIdx.x) >> 5;
    const int lane = threadIdx.x & 31;
    if (warp >= BB * CC) return;
    const int b = warp / CC;

    const int* p = &paths[warp * 3];
    int p0 = __ldg(p), p1 = __ldg(p + 1), p2 = __ldg(p + 2);
    int i0 = min(max(p0, 0), TT - 1);
    int i1 = min(max(p1, 0), TT - 1);
    int i2 = min(max(p2, 0), TT - 1);

    const float* S0 = &d_S[(long)(b * TT + i0) * NPAD];
    const float* S1 = &d_S[(long)(b * TT + i1) * NPAD + 300];
    const float* S2 = &d_S[(long)(b * TT + i2) * NPAD + 600];

    float z0 = 0.f, z1 = 0.f, z2 = 0.f;
    for (int m = lane; m < MLPD; m += 32) {
        float hv = __ldg(&b1[m]);
        if (p0 >= 0) hv += S0[m];
        if (p1 >= 0) hv += S1[m];
        if (p2 >= 0) hv += S2[m];
        hv = tanhf_fast(hv);
        z0 = fmaf(hv, __ldg(&W2[m * 3 + 0]), z0);
        z1 = fmaf(hv, __ldg(&W2[m * 3 + 1]), z1);
        z2 = fmaf(hv, __ldg(&W2[m * 3 + 2]), z2);
    }
#pragma unroll
    for (int off = 16; off; off >>= 1) {
        z0 += __shfl_xor_sync(0xFFFFFFFFu, z0, off);
        z1 += __shfl_xor_sync(0xFFFFFFFFu, z1, off);
        z2 += __shfl_xor_sync(0xFFFFFFFFu, z2, off);
    }
    if (lane == 0) {
        z0 += __ldg(&b2[0]); z1 += __ldg(&b2[1]); z2 += __ldg(&b2[2]);
        float mx = fmaxf(z0, fmaxf(z1, z2));
        float e0 = __expf(z0 - mx), e1 = __expf(z1 - mx), e2 = __expf(z2 - mx);
        float inv = 1.0f / (e0 + e1 + e2);
        out[warp * 3 + 0] = e0 * inv;
        out[warp * 3 + 1] = e1 * inv;
        out[warp * 3 + 2] = e2 * inv;
    }
}

// -------------------------------- launch -----------------------------------------
extern "C" void kernel_launch(void* const* d_in, const int* in_sizes, int n_in,
                              void* d_out, int out_size) {
    const int*   x     = (const int*)  d_in[0];
    const int*   paths = (const int*)  d_in[1];
    const float* emb   = (const float*)d_in[2];
    const float* Whh_f = (const float*)d_in[4];
    const float* Whh_b = (const float*)d_in[8];
    const float* W1    = (const float*)d_in[11];
    const float* b1    = (const float*)d_in[12];
    const float* W2    = (const float*)d_in[13];
    const float* b2    = (const float*)d_in[14];
    float* out = (float*)d_out;

    cudaFuncSetAttribute(gates_gemm_k, cudaFuncAttributeMaxDynamicSharedMemorySize, GEMM_SMEM);
    cudaFuncSetAttribute(s_gemm_k, cudaFuncAttributeMaxDynamicSharedMemorySize, GEMM_SMEM);

    prep_k<<<128, 256>>>((const float*)d_in[3], (const float*)d_in[7],
                         (const float*)d_in[5], (const float*)d_in[6],
                         (const float*)d_in[9], (const float*)d_in[10], W1);

    xet_k<<<256, 512>>>(x, emb);

    { dim3 g(256, 7); gates_gemm_k<<<g, 512, GEMM_SMEM>>>(); }   // 800 cols

    lstm_k<<<128, 800>>>(Whh_f, Whh_b);

    { dim3 g(256, 8); s_gemm_k<<<g, 512, GEMM_SMEM>>>(); }       // 900 cols

    {
        int warps = BB * CC;
        int blocks = (warps * 32 + 255) / 256;
        combine_k<<<blocks, 256>>>(paths, b1, W2, b2, out);
    }
}

// round 9
// speedup vs baseline: 1.1705x; 1.0560x over previous
#include <cuda_runtime.h>
#include <cstdint>
#include <math.h>

#define BB   256
#define TT   128
#define EE   100
#define HH   100
#define CC   255
#define MLPD 300
#define MROWS 32768        // B*T
#define NCG  800           // gin cols (exact)
#define NCS  900           // S cols (exact)

typedef unsigned long long ULL;

__device__ __forceinline__ void ffma2(ULL& acc, ULL a, ULL b) {
    asm volatile("fma.rn.f32x2 %0, %1, %2, %0;" : "+l"(acc) : "l"(a), "l"(b));
}
__device__ __forceinline__ ULL pack2(float x, float y) {
    ULL r; asm("mov.b64 %0, {%1,%2};" : "=l"(r) : "f"(x), "f"(y)); return r;
}
__device__ __forceinline__ float2 unpack2(ULL v) {
    float2 r; asm("mov.b64 {%0,%1}, %2;" : "=f"(r.x), "=f"(r.y) : "l"(v)); return r;
}
__device__ __forceinline__ float tanhf_fast(float x) {
    float r; asm("tanh.approx.f32 %0, %1;" : "=f"(r) : "f"(x)); return r;
}
__device__ __forceinline__ float sigf(float x) { return 0.5f * tanhf_fast(0.5f * x) + 0.5f; }
__device__ __forceinline__ void cp16(void* dst, const void* src) {
    unsigned int d = (unsigned int)__cvta_generic_to_shared(dst);
    asm volatile("cp.async.cg.shared.global [%0], [%1], 16;" :: "r"(d), "l"(src));
}

// ---------------- device-global scratch ----------------------------------------
__device__ ULL   d_xeT[100 * MROWS];        // dup pairs, [k][r], r=t*256+b
__device__ float d_WtIn[100 * NCG];         // [k][col] (400 fwd | 400 bwd)
__device__ float d_bsum[NCG];
__device__ float d_gin[(long)MROWS * NCG];  // [r=t*256+b][col] col = dir*400+gate*100+hid
__device__ ULL   d_h2T[200 * MROWS];        // dup pairs, [k=dir*100+hid][r=b*128+t]
__device__ float d_WtS[200 * NCS];          // [k][s*300+m]
__device__ float d_S[(long)MROWS * NCS];    // [r=b*128+t][col]

// ---------------- prep ----------------------------------------------------------
__global__ void prep_k(const float* __restrict__ Wih_f, const float* __restrict__ Wih_b,
                       const float* __restrict__ bih_f, const float* __restrict__ bhh_f,
                       const float* __restrict__ bih_b, const float* __restrict__ bhh_b,
                       const float* __restrict__ W1) {
    int stride = gridDim.x * blockDim.x;
    int i0 = blockIdx.x * blockDim.x + threadIdx.x;
    for (int idx = i0; idx < 100 * NCG; idx += stride) {
        int k = idx / NCG, col = idx % NCG;
        d_WtIn[idx] = (col < 400) ? Wih_f[col * 100 + k] : Wih_b[(col - 400) * 100 + k];
    }
    for (int idx = i0; idx < NCG; idx += stride) {
        d_bsum[idx] = (idx < 400) ? (bih_f[idx] + bhh_f[idx])
                                  : (bih_b[idx - 400] + bhh_b[idx - 400]);
    }
    for (int idx = i0; idx < 200 * NCS; idx += stride) {
        int k = idx / NCS, col = idx % NCS;
        int s = col / MLPD, m = col % MLPD;
        d_WtS[idx] = W1[(s * 200 + k) * MLPD + m];
    }
}

// ---------------- embed gather + transpose + duplicate --------------------------
__global__ __launch_bounds__(512) void xet_k(const int* __restrict__ x,
                                             const float* __restrict__ emb) {
    __shared__ float sh[128][101];
    __shared__ int toks[128];
    const int tid = threadIdx.x;
    const int r0 = blockIdx.x * 128;
    if (tid < 128) {
        int r = r0 + tid;
        toks[tid] = x[(r & 255) * TT + (r >> 8)];   // r = t*256+b
    }
    __syncthreads();
    for (int idx = tid; idx < 128 * 100; idx += 512) {
        int row = idx / 100, k = idx % 100;
        sh[row][k] = emb[(long)toks[row] * EE + k];
    }
    __syncthreads();
    for (int idx = tid; idx < 100 * 128; idx += 512) {
        int k = idx >> 7, j = idx & 127;
        float v = sh[j][k];
        d_xeT[(long)k * MROWS + r0 + j] = pack2(v, v);
    }
}

// ---------------- GEMM: BM=256, BN=128, BK=20, TM=8, TN=8, cp.async dbl buffer ---
// smem: As[2][20][256] ULL (81920B) + Bs[2][20][128] float (20480B) = 102400B.
#define GEMM_SMEM 102400
template <int KT, bool BIAS>
__device__ __forceinline__ void gemm_body(const ULL* __restrict__ Adup,
                                          const float* __restrict__ Bw,
                                          const float* __restrict__ bias,
                                          float* __restrict__ Cout, int NC) {
    extern __shared__ char smx[];
    ULL*   As = (ULL*)smx;                                   // [2][20][256]
    float* Bs = (float*)(smx + 2 * 20 * 256 * sizeof(ULL));  // [2][20][128]
    const int tid = threadIdx.x;
    const int tx = tid & 15;     // 16 x 8 cols
    const int ty = tid >> 4;     // 32 x 8 rows
    const int r0 = blockIdx.x * 256;
    const int c0 = min((int)blockIdx.y * 128, NC - 128);

    ULL acc[8][4];
    if (BIAS) {
        ulonglong2 b01 = *(const ulonglong2*)&bias[c0 + tx * 8];
        ulonglong2 b23 = *(const ulonglong2*)&bias[c0 + tx * 8 + 4];
#pragma unroll
        for (int i = 0; i < 8; i++) {
            acc[i][0] = b01.x; acc[i][1] = b01.y; acc[i][2] = b23.x; acc[i][3] = b23.y;
        }
    } else {
#pragma unroll
        for (int i = 0; i < 8; i++)
#pragma unroll
            for (int j = 0; j < 4; j++) acc[i][j] = 0ull;
    }

    // prologue: tile 0 -> buf 0
    for (int ch = tid; ch < 3200; ch += 512) {
        if (ch < 2560) {
            int kk = ch >> 7, off = ch & 127;
            cp16((char*)As + kk * 2048 + off * 16,
                 (const char*)(Adup + (long)kk * MROWS + r0) + off * 16);
        } else {
            int c2 = ch - 2560;
            int kk = c2 >> 5, off = c2 & 31;
            cp16((char*)Bs + kk * 512 + off * 16,
                 (const char*)(Bw + (long)kk * NC + c0) + off * 16);
        }
    }
    asm volatile("cp.async.commit_group;");
    asm volatile("cp.async.wait_group 0;");
    __syncthreads();

    for (int kt = 0; kt < KT; kt++) {
        const int p = kt & 1;
        if (kt + 1 < KT) {
            const int kb = (kt + 1) * 20;
            const int pn = p ^ 1;
            for (int ch = tid; ch < 3200; ch += 512) {
                if (ch < 2560) {
                    int kk = ch >> 7, off = ch & 127;
                    cp16((char*)As + pn * 40960 + kk * 2048 + off * 16,
                         (const char*)(Adup + (long)(kb + kk) * MROWS + r0) + off * 16);
                } else {
                    int c2 = ch - 2560;
                    int kk = c2 >> 5, off = c2 & 31;
                    cp16((char*)Bs + pn * 10240 + kk * 512 + off * 16,
                         (const char*)(Bw + (long)(kb + kk) * NC + c0) + off * 16);
                }
            }
            asm volatile("cp.async.commit_group;");
        }
        const ULL*   Ap = As + p * 5120;
        const float* Bp = Bs + p * 2560;
#pragma unroll
        for (int kk = 0; kk < 20; kk++) {
            ulonglong2 b01 = *(const ulonglong2*)&Bp[kk * 128 + tx * 8];
            ulonglong2 b23 = *(const ulonglong2*)&Bp[kk * 128 + tx * 8 + 4];
#pragma unroll
            for (int i2 = 0; i2 < 4; i2++) {
                ulonglong2 a2 = *(const ulonglong2*)&Ap[kk * 256 + ty * 8 + i2 * 2];
                ffma2(acc[i2 * 2][0],     a2.x, b01.x);
                ffma2(acc[i2 * 2][1],     a2.x, b01.y);
                ffma2(acc[i2 * 2][2],     a2.x, b23.x);
                ffma2(acc[i2 * 2][3],     a2.x, b23.y);
                ffma2(acc[i2 * 2 + 1][0], a2.y, b01.x);
                ffma2(acc[i2 * 2 + 1][1], a2.y, b01.y);
                ffma2(acc[i2 * 2 + 1][2], a2.y, b23.x);
                ffma2(acc[i2 * 2 + 1][3], a2.y, b23.y);
            }
        }
        if (kt + 1 < KT) asm volatile("cp.async.wait_group 0;");
        __syncthreads();
    }

#pragma unroll
    for (int i = 0; i < 8; i++) {
        float* co = &Cout[(long)(r0 + ty * 8 + i) * NC + c0 + tx * 8];
        float2 v0 = unpack2(acc[i][0]), v1 = unpack2(acc[i][1]);
        float2 v2 = unpack2(acc[i][2]), v3 = unpack2(acc[i][3]);
        *(float4*)co       = make_float4(v0.x, v0.y, v1.x, v1.y);
        *(float4*)(co + 4) = make_float4(v2.x, v2.y, v3.x, v3.y);
    }
}

__global__ __launch_bounds__(512) void gates_gemm_k() {
    gemm_body<5, true>(d_xeT, d_WtIn, d_bsum, d_gin, NCG);
}
__global__ __launch_bounds__(512) void s_gemm_k() {
    gemm_body<10, false>(d_h2T, d_WtS, nullptr, d_S, NCS);
}

// ---------------- LSTM recurrence: 800 thr, 2 gates/thread, shuffle scatter ------
__global__ __launch_bounds__(800, 1) void lstm_k(const float* __restrict__ Whh_f,
                                                 const float* __restrict__ Whh_b) {
    __shared__ __align__(16) float hs[2][4 * 116];   // [buf][b*116 + hq*28 + i]
    const int tid = threadIdx.x;
    const int dir = blockIdx.x >> 6;
    const int b0 = (blockIdx.x & 63) * 4;
    const float* __restrict__ Whh = dir ? Whh_b : Whh_f;

    const int hid = tid >> 3;
    const int sub = tid & 7;
    const int q = sub >> 1;
    const int gh = sub & 1;
    const int hi2 = (q >> 1) & 1;
    const int lo = q & 1;

    ULL w[2][13];
#pragma unroll
    for (int g2 = 0; g2 < 2; g2++) {
        const float* row = Whh + ((gh * 2 + g2) * 100 + hid) * 100 + q * 25;
#pragma unroll
        for (int p = 0; p < 12; p++) w[g2][p] = pack2(row[2 * p], row[2 * p + 1]);
        w[g2][12] = pack2(row[24], 0.0f);
    }
    for (int idx = tid; idx < 2 * 4 * 116; idx += 800) hs[0][idx] = 0.0f;

    const int hq = hid / 25, hr = hid % 25;
    float c = 0.0f;
    float g0, g1;
    {
        int t0 = dir ? (TT - 1) : 0;
        const float* gp = &d_gin[((long)(t0 * 256 + b0 + q)) * NCG + dir * 400 + gh * 200 + hid];
        g0 = gp[0]; g1 = gp[100];
    }
    __syncthreads();

    for (int step = 0; step < TT; ++step) {
        const int t = dir ? (TT - 1 - step) : step;
        const float* hbuf = hs[step & 1];
        float* hnxt = hs[(step + 1) & 1];

        float v[4][2];
#pragma unroll
        for (int b = 0; b < 4; b++) {
            const float* hb = &hbuf[b * 116 + q * 28];
            ULL a0 = 0ull, a1 = 0ull;
#pragma unroll
            for (int m = 0; m < 6; m++) {
                ulonglong2 hp = *(const ulonglong2*)(hb + 4 * m);
                ffma2(a0, w[0][2 * m], hp.x); ffma2(a0, w[0][2 * m + 1], hp.y);
                ffma2(a1, w[1][2 * m], hp.x); ffma2(a1, w[1][2 * m + 1], hp.y);
            }
            {
                ULL ht = *(const ULL*)(hb + 24);
                ffma2(a0, w[0][12], ht); ffma2(a1, w[1][12], ht);
            }
            float2 f0 = unpack2(a0), f1 = unpack2(a1);
            v[b][0] = f0.x + f0.y;
            v[b][1] = f1.x + f1.y;
        }

        float u[2][2];
#pragma unroll
        for (int j = 0; j < 2; j++)
#pragma unroll
            for (int g = 0; g < 2; g++) {
                float keep = hi2 ? v[2 + j][g] : v[j][g];
                float send = hi2 ? v[j][g]     : v[2 + j][g];
                u[j][g] = keep + __shfl_xor_sync(0xFFFFFFFFu, send, 4);
            }
        float s0, s1;
        {
            float k0 = lo ? u[1][0] : u[0][0];
            float e0 = lo ? u[0][0] : u[1][0];
            s0 = k0 + __shfl_xor_sync(0xFFFFFFFFu, e0, 2);
            float k1 = lo ? u[1][1] : u[0][1];
            float e1 = lo ? u[0][1] : u[1][1];
            s1 = k1 + __shfl_xor_sync(0xFFFFFFFFu, e1, 2);
        }

        float uA = g0 + s0;
        float uB = g1 + s1;
        float oA = __shfl_xor_sync(0xFFFFFFFFu, uA, 1);
        float oB = __shfl_xor_sync(0xFFFFFFFFu, uB, 1);
        float pi = gh ? oA : uA;
        float pf = gh ? oB : uB;
        float pg = gh ? uA : oA;
        float po = gh ? uB : oB;
        c = sigf(pf) * c + sigf(pi) * tanhf_fast(pg);
        float h = sigf(po) * tanhf_fast(c);
        if (gh == 0) {
            hnxt[q * 116 + hq * 28 + hr] = h;
            d_h2T[(long)(dir * 100 + hid) * MROWS + (b0 + q) * TT + t] = pack2(h, h);
        }
        {
            int sn = (step + 1 < TT) ? (step + 1) : step;
            int tn = dir ? (TT - 1 - sn) : sn;
            const float* gp = &d_gin[((long)(tn * 256 + b0 + q)) * NCG + dir * 400 + gh * 200 + hid];
            g0 = gp[0]; g1 = gp[100];
        }
        __syncthreads();
    }
}

// ---------------- combine: gather + tanh + (300->3) + softmax --------------------
__global__ __launch_bounds__(256) void combine_k(const int* __restrict__ paths,
                                                 const float* __restrict__ b1,
                                                 const float* __restrict__ W2,
                                                 const float* __restrict__ b2,
                                                 float* __restrict__ out) {
    const int warp = (blockIdx.x * blockDim.x + threadIdx.x) >> 5;
    const int lane = threadIdx.x & 31;
    if (warp >= BB * CC) return;
    const int b = warp / CC;

    const int* p = &paths[warp * 3];
    int p0 = __ldg(p), p1 = __ldg(p + 1), p2 = __ldg(p + 2);
    int i0 = min(max(p0, 0), TT - 1);
    int i1 = min(max(p1, 0), TT - 1);
    int i2 = min(max(p2, 0), TT - 1);

    const float* S0 = &d_S[(long)(b * TT + i0) * NCS];
    const float* S1 = &d_S[(long)(b * TT + i1) * NCS + 300];
    const float* S2 = &d_S[(long)(b * TT + i2) * NCS + 600];

    float z0 = 0.f, z1 = 0.f, z2 = 0.f;
    for (int m = lane; m < MLPD; m += 32) {
        float hv = __ldg(&b1[m]);
        if (p0 >= 0) hv += S0[m];
        if (p1 >= 0) hv += S1[m];
        if (p2 >= 0) hv += S2[m];
        hv = tanhf_fast(hv);
        z0 = fmaf(hv, __ldg(&W2[m * 3 + 0]), z0);
        z1 = fmaf(hv, __ldg(&W2[m * 3 + 1]), z1);
        z2 = fmaf(hv, __ldg(&W2[m * 3 + 2]), z2);
    }
#pragma unroll
    for (int off = 16; off; off >>= 1) {
        z0 += __shfl_xor_sync(0xFFFFFFFFu, z0, off);
        z1 += __shfl_xor_sync(0xFFFFFFFFu, z1, off);
        z2 += __shfl_xor_sync(0xFFFFFFFFu, z2, off);
    }
    if (lane == 0) {
        z0 += __ldg(&b2[0]); z1 += __ldg(&b2[1]); z2 += __ldg(&b2[2]);
        float mx = fmaxf(z0, fmaxf(z1, z2));
        float e0 = __expf(z0 - mx), e1 = __expf(z1 - mx), e2 = __expf(z2 - mx);
        float inv = 1.0f / (e0 + e1 + e2);
        out[warp * 3 + 0] = e0 * inv;
        out[warp * 3 + 1] = e1 * inv;
        out[warp * 3 + 2] = e2 * inv;
    }
}

// -------------------------------- launch -----------------------------------------
extern "C" void kernel_launch(void* const* d_in, const int* in_sizes, int n_in,
                              void* d_out, int out_size) {
    const int*   x     = (const int*)  d_in[0];
    const int*   paths = (const int*)  d_in[1];
    const float* emb   = (const float*)d_in[2];
    const float* Whh_f = (const float*)d_in[4];
    const float* Whh_b = (const float*)d_in[8];
    const float* W1    = (const float*)d_in[11];
    const float* b1    = (const float*)d_in[12];
    const float* W2    = (const float*)d_in[13];
    const float* b2    = (const float*)d_in[14];
    float* out = (float*)d_out;

    cudaFuncSetAttribute(gates_gemm_k, cudaFuncAttributeMaxDynamicSharedMemorySize, GEMM_SMEM);
    cudaFuncSetAttribute(s_gemm_k, cudaFuncAttributeMaxDynamicSharedMemorySize, GEMM_SMEM);

    prep_k<<<128, 256>>>((const float*)d_in[3], (const float*)d_in[7],
                         (const float*)d_in[5], (const float*)d_in[6],
                         (const float*)d_in[9], (const float*)d_in[10], W1);

    xet_k<<<256, 512>>>(x, emb);

    { dim3 g(128, 7); gates_gemm_k<<<g, 512, GEMM_SMEM>>>(); }   // 800 cols

    lstm_k<<<128, 800>>>(Whh_f, Whh_b);

    { dim3 g(128, 8); s_gemm_k<<<g, 512, GEMM_SMEM>>>(); }       // 900 cols

    {
        int warps = BB * CC;
        int blocks = (warps * 32 + 255) / 256;
        combine_k<<<blocks, 256>>>(paths, b1, W2, b2, out);
    }
}

// round 11
// speedup vs baseline: 1.5811x; 1.3507x over previous
#include <cuda_runtime.h>
#include <cuda_bf16.h>
#include <cstdint>
#include <math.h>

#define BB   256
#define TT   128
#define EE   100
#define HH   100
#define CC   255
#define MLPD 300
#define MROWS 32768        // B*T
#define NCG  800           // gin cols (exact)
#define NCS  900           // S cols (exact)
#define KPAD 256           // padded K storage (200 real, GEMM uses 224)

typedef unsigned long long ULL;

__device__ __forceinline__ void ffma2(ULL& acc, ULL a, ULL b) {
    asm volatile("fma.rn.f32x2 %0, %1, %2, %0;" : "+l"(acc) : "l"(a), "l"(b));
}
__device__ __forceinline__ ULL pack2(float x, float y) {
    ULL r; asm("mov.b64 %0, {%1,%2};" : "=l"(r) : "f"(x), "f"(y)); return r;
}
__device__ __forceinline__ float2 unpack2(ULL v) {
    float2 r; asm("mov.b64 {%0,%1}, %2;" : "=f"(r.x), "=f"(r.y) : "l"(v)); return r;
}
__device__ __forceinline__ float tanhf_fast(float x) {
    float r; asm("tanh.approx.f32 %0, %1;" : "=f"(r) : "f"(x)); return r;
}
__device__ __forceinline__ float sigf(float x) { return 0.5f * tanhf_fast(0.5f * x) + 0.5f; }
__device__ __forceinline__ void cp16(void* dst, const void* src) {
    unsigned int d = (unsigned int)__cvta_generic_to_shared(dst);
    asm volatile("cp.async.cg.shared.global [%0], [%1], 16;" :: "r"(d), "l"(src));
}
__device__ __forceinline__ void cp16s(unsigned int dst, const void* src) {
    asm volatile("cp.async.cg.shared.global [%0], [%1], 16;" :: "r"(dst), "l"(src));
}
__device__ __forceinline__ unsigned int smem_u32(const void* p) {
    return (unsigned int)__cvta_generic_to_shared(p);
}
__device__ __forceinline__ void ldm_x4(unsigned int& r0, unsigned int& r1,
                                       unsigned int& r2, unsigned int& r3,
                                       unsigned int addr) {
    asm volatile("ldmatrix.sync.aligned.m8n8.x4.shared.b16 {%0,%1,%2,%3}, [%4];"
                 : "=r"(r0), "=r"(r1), "=r"(r2), "=r"(r3) : "r"(addr));
}
__device__ __forceinline__ void mma16816(float* d, const unsigned int* a,
                                         const unsigned int* b) {
    asm volatile(
        "mma.sync.aligned.m16n8k16.row.col.f32.bf16.bf16.f32 "
        "{%0,%1,%2,%3}, {%4,%5,%6,%7}, {%8,%9}, {%0,%1,%2,%3};"
        : "+f"(d[0]), "+f"(d[1]), "+f"(d[2]), "+f"(d[3])
        : "r"(a[0]), "r"(a[1]), "r"(a[2]), "r"(a[3]), "r"(b[0]), "r"(b[1]));
}

// ---------------- device-global scratch ----------------------------------------
__device__ ULL   d_xeT[100 * MROWS];                  // dup pairs, [k][r], r=t*256+b
__device__ float d_WtIn[100 * NCG];                   // [k][col]
__device__ float d_bsum[NCG];
__device__ float d_gin[(long)MROWS * NCG];            // [r=t*256+b][col]
__device__ __nv_bfloat16 d_Ahi[(long)MROWS * KPAD];   // [r=b*128+t][k]
__device__ __nv_bfloat16 d_Alo[(long)MROWS * KPAD];
__device__ __nv_bfloat16 d_Bhi[NCS * KPAD];           // [col][k]
__device__ __nv_bfloat16 d_Blo[NCS * KPAD];
__device__ float d_S[(long)MROWS * NCS];              // [r=b*128+t][col]

// ---------------- prep ----------------------------------------------------------
__global__ void prep_k(const float* __restrict__ Wih_f, const float* __restrict__ Wih_b,
                       const float* __restrict__ bih_f, const float* __restrict__ bhh_f,
                       const float* __restrict__ bih_b, const float* __restrict__ bhh_b,
                       const float* __restrict__ W1) {
    int stride = gridDim.x * blockDim.x;
    int i0 = blockIdx.x * blockDim.x + threadIdx.x;
    for (int idx = i0; idx < 100 * NCG; idx += stride) {
        int k = idx / NCG, col = idx % NCG;
        d_WtIn[idx] = (col < 400) ? Wih_f[col * 100 + k] : Wih_b[(col - 400) * 100 + k];
    }
    for (int idx = i0; idx < NCG; idx += stride) {
        d_bsum[idx] = (idx < 400) ? (bih_f[idx] + bhh_f[idx])
                                  : (bih_b[idx - 400] + bhh_b[idx - 400]);
    }
    for (int idx = i0; idx < NCS * KPAD; idx += stride) {
        int col = idx / KPAD, k = idx % KPAD;
        float v = 0.0f;
        if (k < 200) {
            int s = col / MLPD, m = col % MLPD;
            v = W1[(s * 200 + k) * MLPD + m];
        }
        __nv_bfloat16 hi = __float2bfloat16(v);
        __nv_bfloat16 lo = __float2bfloat16(v - __bfloat162float(hi));
        d_Bhi[idx] = hi;
        d_Blo[idx] = lo;
    }
    for (int idx = i0; idx < MROWS * (KPAD - 200); idx += stride) {
        int r = idx / (KPAD - 200), k = 200 + idx % (KPAD - 200);
        d_Ahi[(long)r * KPAD + k] = __float2bfloat16(0.0f);
        d_Alo[(long)r * KPAD + k] = __float2bfloat16(0.0f);
    }
}

// ---------------- embed gather + transpose + duplicate --------------------------
__global__ __launch_bounds__(512) void xet_k(const int* __restrict__ x,
                                             const float* __restrict__ emb) {
    __shared__ float sh[128][101];
    __shared__ int toks[128];
    const int tid = threadIdx.x;
    const int r0 = blockIdx.x * 128;
    if (tid < 128) {
        int r = r0 + tid;
        toks[tid] = x[(r & 255) * TT + (r >> 8)];   // r = t*256+b
    }
    __syncthreads();
    for (int idx = tid; idx < 128 * 100; idx += 512) {
        int row = idx / 100, k = idx % 100;
        sh[row][k] = emb[(long)toks[row] * EE + k];
    }
    __syncthreads();
    for (int idx = tid; idx < 100 * 128; idx += 512) {
        int k = idx >> 7, j = idx & 127;
        float v = sh[j][k];
        d_xeT[(long)k * MROWS + r0 + j] = pack2(v, v);
    }
}

// ---------------- gates GEMM (FFMA2): BM=256, BN=128, BK=20, TM=8, TN=8 ----------
#define GEMM_SMEM 102400
template <int KT, bool BIAS>
__device__ __forceinline__ void gemm_body(const ULL* __restrict__ Adup,
                                          const float* __restrict__ Bw,
                                          const float* __restrict__ bias,
                                          float* __restrict__ Cout, int NC) {
    extern __shared__ char smx[];
    ULL*   As = (ULL*)smx;                                   // [2][20][256]
    float* Bs = (float*)(smx + 2 * 20 * 256 * sizeof(ULL));  // [2][20][128]
    const int tid = threadIdx.x;
    const int tx = tid & 15;
    const int ty = tid >> 4;
    const int r0 = blockIdx.x * 256;
    const int c0 = min((int)blockIdx.y * 128, NC - 128);

    ULL acc[8][4];
    if (BIAS) {
        ulonglong2 b01 = *(const ulonglong2*)&bias[c0 + tx * 8];
        ulonglong2 b23 = *(const ulonglong2*)&bias[c0 + tx * 8 + 4];
#pragma unroll
        for (int i = 0; i < 8; i++) {
            acc[i][0] = b01.x; acc[i][1] = b01.y; acc[i][2] = b23.x; acc[i][3] = b23.y;
        }
    } else {
#pragma unroll
        for (int i = 0; i < 8; i++)
#pragma unroll
            for (int j = 0; j < 4; j++) acc[i][j] = 0ull;
    }

    for (int ch = tid; ch < 3200; ch += 512) {
        if (ch < 2560) {
            int kk = ch >> 7, off = ch & 127;
            cp16((char*)As + kk * 2048 + off * 16,
                 (const char*)(Adup + (long)kk * MROWS + r0) + off * 16);
        } else {
            int c2 = ch - 2560;
            int kk = c2 >> 5, off = c2 & 31;
            cp16((char*)Bs + kk * 512 + off * 16,
                 (const char*)(Bw + (long)kk * NC + c0) + off * 16);
        }
    }
    asm volatile("cp.async.commit_group;");
    asm volatile("cp.async.wait_group 0;");
    __syncthreads();

    for (int kt = 0; kt < KT; kt++) {
        const int p = kt & 1;
        if (kt + 1 < KT) {
            const int kb = (kt + 1) * 20;
            const int pn = p ^ 1;
            for (int ch = tid; ch < 3200; ch += 512) {
                if (ch < 2560) {
                    int kk = ch >> 7, off = ch & 127;
                    cp16((char*)As + pn * 40960 + kk * 2048 + off * 16,
                         (const char*)(Adup + (long)(kb + kk) * MROWS + r0) + off * 16);
                } else {
                    int c2 = ch - 2560;
                    int kk = c2 >> 5, off = c2 & 31;
                    cp16((char*)Bs + pn * 10240 + kk * 512 + off * 16,
                         (const char*)(Bw + (long)(kb + kk) * NC + c0) + off * 16);
                }
            }
            asm volatile("cp.async.commit_group;");
        }
        const ULL*   Ap = As + p * 5120;
        const float* Bp = Bs + p * 2560;
#pragma unroll
        for (int kk = 0; kk < 20; kk++) {
            ulonglong2 b01 = *(const ulonglong2*)&Bp[kk * 128 + tx * 8];
            ulonglong2 b23 = *(const ulonglong2*)&Bp[kk * 128 + tx * 8 + 4];
#pragma unroll
            for (int i2 = 0; i2 < 4; i2++) {
                ulonglong2 a2 = *(const ulonglong2*)&Ap[kk * 256 + ty * 8 + i2 * 2];
                ffma2(acc[i2 * 2][0],     a2.x, b01.x);
                ffma2(acc[i2 * 2][1],     a2.x, b01.y);
                ffma2(acc[i2 * 2][2],     a2.x, b23.x);
                ffma2(acc[i2 * 2][3],     a2.x, b23.y);
                ffma2(acc[i2 * 2 + 1][0], a2.y, b01.x);
                ffma2(acc[i2 * 2 + 1][1], a2.y, b01.y);
                ffma2(acc[i2 * 2 + 1][2], a2.y, b23.x);
                ffma2(acc[i2 * 2 + 1][3], a2.y, b23.y);
            }
        }
        if (kt + 1 < KT) asm volatile("cp.async.wait_group 0;");
        __syncthreads();
    }

#pragma unroll
    for (int i = 0; i < 8; i++) {
        float* co = &Cout[(long)(r0 + ty * 8 + i) * NC + c0 + tx * 8];
        float2 v0 = unpack2(acc[i][0]), v1 = unpack2(acc[i][1]);
        float2 v2 = unpack2(acc[i][2]), v3 = unpack2(acc[i][3]);
        *(float4*)co       = make_float4(v0.x, v0.y, v1.x, v1.y);
        *(float4*)(co + 4) = make_float4(v2.x, v2.y, v3.x, v3.y);
    }
}

__global__ __launch_bounds__(512) void gates_gemm_k() {
    gemm_body<5, true>(d_xeT, d_WtIn, d_bsum, d_gin, NCG);
}

// ---------------- LSTM recurrence (bf16 hi/lo h output) --------------------------
__global__ __launch_bounds__(800, 1) void lstm_k(const float* __restrict__ Whh_f,
                                                 const float* __restrict__ Whh_b) {
    __shared__ __align__(16) float hs[2][4 * 116];
    const int tid = threadIdx.x;
    const int dir = blockIdx.x >> 6;
    const int b0 = (blockIdx.x & 63) * 4;
    const float* __restrict__ Whh = dir ? Whh_b : Whh_f;

    const int hid = tid >> 3;
    const int sub = tid & 7;
    const int q = sub >> 1;
    const int gh = sub & 1;
    const int hi2 = (q >> 1) & 1;
    const int lo = q & 1;

    ULL w[2][13];
#pragma unroll
    for (int g2 = 0; g2 < 2; g2++) {
        const float* row = Whh + ((gh * 2 + g2) * 100 + hid) * 100 + q * 25;
#pragma unroll
        for (int p = 0; p < 12; p++) w[g2][p] = pack2(row[2 * p], row[2 * p + 1]);
        w[g2][12] = pack2(row[24], 0.0f);
    }
    for (int idx = tid; idx < 2 * 4 * 116; idx += 800) hs[0][idx] = 0.0f;

    const int hq = hid / 25, hr = hid % 25;
    float c = 0.0f;
    float g0, g1;
    {
        int t0 = dir ? (TT - 1) : 0;
        const float* gp = &d_gin[((long)(t0 * 256 + b0 + q)) * NCG + dir * 400 + gh * 200 + hid];
        g0 = gp[0]; g1 = gp[100];
    }
    __syncthreads();

    for (int step = 0; step < TT; ++step) {
        const int t = dir ? (TT - 1 - step) : step;
        const float* hbuf = hs[step & 1];
        float* hnxt = hs[(step + 1) & 1];

        float v[4][2];
#pragma unroll
        for (int b = 0; b < 4; b++) {
            const float* hb = &hbuf[b * 116 + q * 28];
            ULL a0 = 0ull, a1 = 0ull;
#pragma unroll
            for (int m = 0; m < 6; m++) {
                ulonglong2 hp = *(const ulonglong2*)(hb + 4 * m);
                ffma2(a0, w[0][2 * m], hp.x); ffma2(a0, w[0][2 * m + 1], hp.y);
                ffma2(a1, w[1][2 * m], hp.x); ffma2(a1, w[1][2 * m + 1], hp.y);
            }
            {
                ULL ht = *(const ULL*)(hb + 24);
                ffma2(a0, w[0][12], ht); ffma2(a1, w[1][12], ht);
            }
            float2 f0 = unpack2(a0), f1 = unpack2(a1);
            v[b][0] = f0.x + f0.y;
            v[b][1] = f1.x + f1.y;
        }

        float u[2][2];
#pragma unroll
        for (int j = 0; j < 2; j++)
#pragma unroll
            for (int g = 0; g < 2; g++) {
                float keep = hi2 ? v[2 + j][g] : v[j][g];
                float send = hi2 ? v[j][g]     : v[2 + j][g];
                u[j][g] = keep + __shfl_xor_sync(0xFFFFFFFFu, send, 4);
            }
        float s0, s1;
        {
            float k0 = lo ? u[1][0] : u[0][0];
            float e0 = lo ? u[0][0] : u[1][0];
            s0 = k0 + __shfl_xor_sync(0xFFFFFFFFu, e0, 2);
            float k1 = lo ? u[1][1] : u[0][1];
            float e1 = lo ? u[0][1] : u[1][1];
            s1 = k1 + __shfl_xor_sync(0xFFFFFFFFu, e1, 2);
        }

        float uA = g0 + s0;
        float uB = g1 + s1;
        float oA = __shfl_xor_sync(0xFFFFFFFFu, uA, 1);
        float oB = __shfl_xor_sync(0xFFFFFFFFu, uB, 1);
        float pi = gh ? oA : uA;
        float pf = gh ? oB : uB;
        float pg = gh ? uA : oA;
        float po = gh ? uB : oB;
        c = sigf(pf) * c + sigf(pi) * tanhf_fast(pg);
        float h = sigf(po) * tanhf_fast(c);
        if (gh == 0) {
            hnxt[q * 116 + hq * 28 + hr] = h;
            long r = (long)(b0 + q) * TT + t;
            __nv_bfloat16 bh = __float2bfloat16(h);
            __nv_bfloat16 bl = __float2bfloat16(h - __bfloat162float(bh));
            d_Ahi[r * KPAD + dir * 100 + hid] = bh;
            d_Alo[r * KPAD + dir * 100 + hid] = bl;
        }
        {
            int sn = (step + 1 < TT) ? (step + 1) : step;
            int tn = dir ? (TT - 1 - sn) : sn;
            const float* gp = &d_gin[((long)(tn * 256 + b0 + q)) * NCG + dir * 400 + gh * 200 + hid];
            g0 = gp[0]; g1 = gp[100];
        }
        __syncthreads();
    }
}

// ---------------- S-GEMM: mma.sync bf16 split-3, BM=128 BN=128 BK=32 -------------
// 256 threads / 8 warps (wr = wid>>1 in 0..3, wc = wid&1): warp tile 32x64.
// smem: 2 buffers x 4 arrays (Ahi,Alo,Bhi,Blo) x [128 rows][40 bf16] (80B pitch).
// K = 224 (7 tiles of 32); zero-padded beyond 200.
#define STC_SMEM (2 * 4 * 128 * 80)   // 81920 bytes
__global__ __launch_bounds__(256, 2) void s_tc_k() {
    extern __shared__ char smx[];
    const unsigned int tile = smem_u32(smx);
    const int tid = threadIdx.x;
    const int wid = tid >> 5;
    const int lane = tid & 31;
    const int wr = wid >> 1;
    const int wc = wid & 1;
    const int r0 = blockIdx.x * 128;
    const int cb = min((int)blockIdx.y * 128, NCS - 128);

    float acc[2][8][4];
#pragma unroll
    for (int mt = 0; mt < 2; mt++)
#pragma unroll
        for (int nt = 0; nt < 8; nt++)
#pragma unroll
            for (int j = 0; j < 4; j++) acc[mt][nt][j] = 0.0f;

    // ---- fill helper (inlined twice) ----
    // buffer layout: buf*40960 + arr*10240 + row*80 + c4*16
#define FILL_TILE(KC, BUF) do { \
    for (int u = tid; u < 2048; u += 256) { \
        int arr = u >> 9; \
        int rem = u & 511; \
        int row = rem >> 2; \
        int c4 = rem & 3; \
        const __nv_bfloat16* src; \
        if (arr == 0)      src = &d_Ahi[(long)(r0 + row) * KPAD + (KC) + c4 * 8]; \
        else if (arr == 1) src = &d_Alo[(long)(r0 + row) * KPAD + (KC) + c4 * 8]; \
        else if (arr == 2) src = &d_Bhi[(long)(cb + row) * KPAD + (KC) + c4 * 8]; \
        else               src = &d_Blo[(long)(cb + row) * KPAD + (KC) + c4 * 8]; \
        cp16s(tile + (BUF) * 40960 + arr * 10240 + row * 80 + c4 * 16, src); \
    } \
    asm volatile("cp.async.commit_group;"); \
} while (0)

    FILL_TILE(0, 0);

    for (int kt = 0; kt < 7; kt++) {
        const int p = kt & 1;
        if (kt + 1 < 7) {
            FILL_TILE((kt + 1) * 32, p ^ 1);
            asm volatile("cp.async.wait_group 1;");
        } else {
            asm volatile("cp.async.wait_group 0;");
        }
        __syncthreads();

        const unsigned int bufb = tile + p * 40960;
        const unsigned int Ahib = bufb;
        const unsigned int Alob = bufb + 10240;
        const unsigned int Bhib = bufb + 20480;
        const unsigned int Blob = bufb + 30720;

#pragma unroll
        for (int ks = 0; ks < 2; ks++) {
            // A fragments: 2 m-tiles x (hi, lo)
            unsigned int ahi[2][4], alo[2][4];
#pragma unroll
            for (int mt = 0; mt < 2; mt++) {
                int row = wr * 32 + mt * 16 + (lane & 15);
                unsigned int koff = ((lane >> 4) * 8 + ks * 16) * 2;
                ldm_x4(ahi[mt][0], ahi[mt][1], ahi[mt][2], ahi[mt][3],
                       Ahib + row * 80 + koff);
                ldm_x4(alo[mt][0], alo[mt][1], alo[mt][2], alo[mt][3],
                       Alob + row * 80 + koff);
            }
            // B fragments in pairs of n-tiles; consume immediately
#pragma unroll
            for (int jn = 0; jn < 4; jn++) {
                int nrow = wc * 64 + jn * 16 + ((lane >> 4) * 8) + (lane & 7);
                unsigned int koff = (ks * 16 + ((lane >> 3) & 1) * 8) * 2;
                unsigned int bhi[4], blo[4];
                ldm_x4(bhi[0], bhi[1], bhi[2], bhi[3], Bhib + nrow * 80 + koff);
                ldm_x4(blo[0], blo[1], blo[2], blo[3], Blob + nrow * 80 + koff);
#pragma unroll
                for (int half = 0; half < 2; half++) {
                    int nt = jn * 2 + half;
#pragma unroll
                    for (int mt = 0; mt < 2; mt++) {
                        mma16816(acc[mt][nt], ahi[mt], bhi + half * 2);
                        mma16816(acc[mt][nt], ahi[mt], blo + half * 2);
                        mma16816(acc[mt][nt], alo[mt], bhi + half * 2);
                    }
                }
            }
        }
        __syncthreads();
    }

    // epilogue: C fragment layout (m16n8): c0,c1 row T/4 cols (T%4)*2,+1; c2,c3 row+8
#pragma unroll
    for (int mt = 0; mt < 2; mt++)
#pragma unroll
        for (int nt = 0; nt < 8; nt++) {
            int rg = r0 + wr * 32 + mt * 16 + (lane >> 2);
            int cg = cb + wc * 64 + nt * 8 + (lane & 3) * 2;
            *(float2*)&d_S[(long)rg * NCS + cg] =
                make_float2(acc[mt][nt][0], acc[mt][nt][1]);
            *(float2*)&d_S[(long)(rg + 8) * NCS + cg] =
                make_float2(acc[mt][nt][2], acc[mt][nt][3]);
        }
#undef FILL_TILE
}

// ---------------- combine: gather + tanh + (300->3) + softmax --------------------
__global__ __launch_bounds__(256) void combine_k(const int* __restrict__ paths,
                                                 const float* __restrict__ b1,
                                                 const float* __restrict__ W2,
                                                 const float* __restrict__ b2,
                                                 float* __restrict__ out) {
    const int warp = (blockIdx.x * blockDim.x + threadIdx.x) >> 5;
    const int lane = threadIdx.x & 31;
    if (warp >= BB * CC) return;
    const int b = warp / CC;

    const int* p = &paths[warp * 3];
    int p0 = __ldg(p), p1 = __ldg(p + 1), p2 = __ldg(p + 2);
    int i0 = min(max(p0, 0), TT - 1);
    int i1 = min(max(p1, 0), TT - 1);
    int i2 = min(max(p2, 0), TT - 1);

    const float* S0 = &d_S[(long)(b * TT + i0) * NCS];
    const float* S1 = &d_S[(long)(b * TT + i1) * NCS + 300];
    const float* S2 = &d_S[(long)(b * TT + i2) * NCS + 600];

    float z0 = 0.f, z1 = 0.f, z2 = 0.f;
    for (int m = lane; m < MLPD; m += 32) {
        float hv = __ldg(&b1[m]);
        if (p0 >= 0) hv += S0[m];
        if (p1 >= 0) hv += S1[m];
        if (p2 >= 0) hv += S2[m];
        hv = tanhf_fast(hv);
        z0 = fmaf(hv, __ldg(&W2[m * 3 + 0]), z0);
        z1 = fmaf(hv, __ldg(&W2[m * 3 + 1]), z1);
        z2 = fmaf(hv, __ldg(&W2[m * 3 + 2]), z2);
    }
#pragma unroll
    for (int off = 16; off; off >>= 1) {
        z0 += __shfl_xor_sync(0xFFFFFFFFu, z0, off);
        z1 += __shfl_xor_sync(0xFFFFFFFFu, z1, off);
        z2 += __shfl_xor_sync(0xFFFFFFFFu, z2, off);
    }
    if (lane == 0) {
        z0 += __ldg(&b2[0]); z1 += __ldg(&b2[1]); z2 += __ldg(&b2[2]);
        float mx = fmaxf(z0, fmaxf(z1, z2));
        float e0 = __expf(z0 - mx), e1 = __expf(z1 - mx), e2 = __expf(z2 - mx);
        float inv = 1.0f / (e0 + e1 + e2);
        out[warp * 3 + 0] = e0 * inv;
        out[warp * 3 + 1] = e1 * inv;
        out[warp * 3 + 2] = e2 * inv;
    }
}

// -------------------------------- launch -----------------------------------------
extern "C" void kernel_launch(void* const* d_in, const int* in_sizes, int n_in,
                              void* d_out, int out_size) {
    const int*   x     = (const int*)  d_in[0];
    const int*   paths = (const int*)  d_in[1];
    const float* emb   = (const float*)d_in[2];
    const float* Whh_f = (const float*)d_in[4];
    const float* Whh_b = (const float*)d_in[8];
    const float* W1    = (const float*)d_in[11];
    const float* b1    = (const float*)d_in[12];
    const float* W2    = (const float*)d_in[13];
    const float* b2    = (const float*)d_in[14];
    float* out = (float*)d_out;

    cudaFuncSetAttribute(gates_gemm_k, cudaFuncAttributeMaxDynamicSharedMemorySize, GEMM_SMEM);
    cudaFuncSetAttribute(s_tc_k, cudaFuncAttributeMaxDynamicSharedMemorySize, STC_SMEM);

    prep_k<<<128, 256>>>((const float*)d_in[3], (const float*)d_in[7],
                         (const float*)d_in[5], (const float*)d_in[6],
                         (const float*)d_in[9], (const float*)d_in[10], W1);

    xet_k<<<256, 512>>>(x, emb);

    { dim3 g(128, 7); gates_gemm_k<<<g, 512, GEMM_SMEM>>>(); }   // 800 cols

    lstm_k<<<128, 800>>>(Whh_f, Whh_b);

    { dim3 g(256, 8); s_tc_k<<<g, 256, STC_SMEM>>>(); }          // HMMA S GEMM

    {
        int warps = BB * CC;
        int blocks = (warps * 32 + 255) / 256;
        combine_k<<<blocks, 256>>>(paths, b1, W2, b2, out);
    }
}

// round 12
// speedup vs baseline: 1.8940x; 1.1979x over previous
#include <cuda_runtime.h>
#include <cuda_bf16.h>
#include <cstdint>
#include <math.h>

#define BB   256
#define TT   128
#define EE   100
#define HH   100
#define CC   255
#define MLPD 300
#define MROWS 32768        // B*T
#define NCG  800           // gin cols (exact)
#define NCS  900           // S cols (exact)
#define KPAD 256           // padded K storage for h2 (200 real, GEMM uses 224)
#define KPX  128           // padded K for embeddings (100 real)

typedef unsigned long long ULL;

__device__ __forceinline__ void ffma2(ULL& acc, ULL a, ULL b) {
    asm volatile("fma.rn.f32x2 %0, %1, %2, %0;" : "+l"(acc) : "l"(a), "l"(b));
}
__device__ __forceinline__ ULL pack2(float x, float y) {
    ULL r; asm("mov.b64 %0, {%1,%2};" : "=l"(r) : "f"(x), "f"(y)); return r;
}
__device__ __forceinline__ float2 unpack2(ULL v) {
    float2 r; asm("mov.b64 {%0,%1}, %2;" : "=f"(r.x), "=f"(r.y) : "l"(v)); return r;
}
__device__ __forceinline__ float tanhf_fast(float x) {
    float r; asm("tanh.approx.f32 %0, %1;" : "=f"(r) : "f"(x)); return r;
}
__device__ __forceinline__ float sigf(float x) { return 0.5f * tanhf_fast(0.5f * x) + 0.5f; }
__device__ __forceinline__ void cp16s(unsigned int dst, const void* src) {
    asm volatile("cp.async.cg.shared.global [%0], [%1], 16;" :: "r"(dst), "l"(src));
}
__device__ __forceinline__ unsigned int smem_u32(const void* p) {
    return (unsigned int)__cvta_generic_to_shared(p);
}
__device__ __forceinline__ void ldm_x4(unsigned int& r0, unsigned int& r1,
                                       unsigned int& r2, unsigned int& r3,
                                       unsigned int addr) {
    asm volatile("ldmatrix.sync.aligned.m8n8.x4.shared.b16 {%0,%1,%2,%3}, [%4];"
                 : "=r"(r0), "=r"(r1), "=r"(r2), "=r"(r3) : "r"(addr));
}
__device__ __forceinline__ void mma16816(float* d, const unsigned int* a,
                                         const unsigned int* b) {
    asm volatile(
        "mma.sync.aligned.m16n8k16.row.col.f32.bf16.bf16.f32 "
        "{%0,%1,%2,%3}, {%4,%5,%6,%7}, {%8,%9}, {%0,%1,%2,%3};"
        : "+f"(d[0]), "+f"(d[1]), "+f"(d[2]), "+f"(d[3])
        : "r"(a[0]), "r"(a[1]), "r"(a[2]), "r"(a[3]), "r"(b[0]), "r"(b[1]));
}

// ---------------- device-global scratch ----------------------------------------
__device__ float d_bsum[NCG];
__device__ __nv_bfloat16 d_Xhi[(long)MROWS * KPX];    // embeddings [r=t*256+b][k]
__device__ __nv_bfloat16 d_Xlo[(long)MROWS * KPX];
__device__ __nv_bfloat16 d_Ghi[NCG * KPX];            // Wih [col][k]
__device__ __nv_bfloat16 d_Glo[NCG * KPX];
__device__ float d_gin[(long)MROWS * NCG];            // [r=t*256+b][col]
__device__ __nv_bfloat16 d_Ahi[(long)MROWS * KPAD];   // h2 [r=b*128+t][k]
__device__ __nv_bfloat16 d_Alo[(long)MROWS * KPAD];
__device__ __nv_bfloat16 d_Bhi[NCS * KPAD];           // W1 [col][k]
__device__ __nv_bfloat16 d_Blo[NCS * KPAD];
__device__ float d_S[(long)MROWS * NCS];              // [r=b*128+t][col]

// ---------------- prep ----------------------------------------------------------
__global__ void prep_k(const float* __restrict__ Wih_f, const float* __restrict__ Wih_b,
                       const float* __restrict__ bih_f, const float* __restrict__ bhh_f,
                       const float* __restrict__ bih_b, const float* __restrict__ bhh_b,
                       const float* __restrict__ W1) {
    int stride = gridDim.x * blockDim.x;
    int i0 = blockIdx.x * blockDim.x + threadIdx.x;
    for (int idx = i0; idx < NCG; idx += stride) {
        d_bsum[idx] = (idx < 400) ? (bih_f[idx] + bhh_f[idx])
                                  : (bih_b[idx - 400] + bhh_b[idx - 400]);
    }
    // Wih -> [col][k] bf16 hi/lo (k pad 128)
    for (int idx = i0; idx < NCG * KPX; idx += stride) {
        int col = idx / KPX, k = idx % KPX;
        float v = 0.0f;
        if (k < 100)
            v = (col < 400) ? Wih_f[col * 100 + k] : Wih_b[(col - 400) * 100 + k];
        __nv_bfloat16 hi = __float2bfloat16(v);
        d_Ghi[idx] = hi;
        d_Glo[idx] = __float2bfloat16(v - __bfloat162float(hi));
    }
    // W1 -> [col][k] bf16 hi/lo (k pad 256)
    for (int idx = i0; idx < NCS * KPAD; idx += stride) {
        int col = idx / KPAD, k = idx % KPAD;
        float v = 0.0f;
        if (k < 200) {
            int s = col / MLPD, m = col % MLPD;
            v = W1[(s * 200 + k) * MLPD + m];
        }
        __nv_bfloat16 hi = __float2bfloat16(v);
        d_Bhi[idx] = hi;
        d_Blo[idx] = __float2bfloat16(v - __bfloat162float(hi));
    }
    // zero k-pad of h2 (k = 200..255)
    for (int idx = i0; idx < MROWS * (KPAD - 200); idx += stride) {
        int r = idx / (KPAD - 200), k = 200 + idx % (KPAD - 200);
        d_Ahi[(long)r * KPAD + k] = __float2bfloat16(0.0f);
        d_Alo[(long)r * KPAD + k] = __float2bfloat16(0.0f);
    }
}

// ---------------- embed gather -> bf16 hi/lo ------------------------------------
__global__ __launch_bounds__(512) void xet_k(const int* __restrict__ x,
                                             const float* __restrict__ emb) {
    __shared__ int toks[128];
    const int tid = threadIdx.x;
    const int r0 = blockIdx.x * 128;
    if (tid < 128) {
        int r = r0 + tid;
        toks[tid] = x[(r & 255) * TT + (r >> 8)];   // r = t*256+b
    }
    __syncthreads();
    for (int idx = tid; idx < 128 * KPX; idx += 512) {
        int row = idx >> 7, k = idx & 127;
        float v = (k < 100) ? emb[(long)toks[row] * EE + k] : 0.0f;
        __nv_bfloat16 hi = __float2bfloat16(v);
        long o = (long)(r0 + row) * KPX + k;
        d_Xhi[o] = hi;
        d_Xlo[o] = __float2bfloat16(v - __bfloat162float(hi));
    }
}

// ---------------- HMMA split-bf16 GEMM template ----------------------------------
// BM=128 BN=128 BK=32, 256 threads / 8 warps (warp tile 32x64), double-buffered
// cp.async smem: 2 bufs x 4 arrays x [128 rows][40 bf16] (80B pitch) = 81920 B.
#define STC_SMEM (2 * 4 * 128 * 80)
template <int KT, int KS, bool BIAS>
__device__ __forceinline__ void tc_gemm(const __nv_bfloat16* __restrict__ Ahi,
                                        const __nv_bfloat16* __restrict__ Alo,
                                        const __nv_bfloat16* __restrict__ Bhi,
                                        const __nv_bfloat16* __restrict__ Blo,
                                        float* __restrict__ C, int NC,
                                        const float* __restrict__ bias) {
    extern __shared__ char smx[];
    const unsigned int tile = smem_u32(smx);
    const int tid = threadIdx.x;
    const int wid = tid >> 5;
    const int lane = tid & 31;
    const int wr = wid >> 1;
    const int wc = wid & 1;
    const int r0 = blockIdx.x * 128;
    const int cb = min((int)blockIdx.y * 128, NC - 128);

    float acc[2][8][4];
#pragma unroll
    for (int mt = 0; mt < 2; mt++)
#pragma unroll
        for (int nt = 0; nt < 8; nt++)
#pragma unroll
            for (int j = 0; j < 4; j++) acc[mt][nt][j] = 0.0f;

#define FILL_TILE(KC, BUF) do { \
    for (int u = tid; u < 2048; u += 256) { \
        int arr = u >> 9; \
        int rem = u & 511; \
        int row = rem >> 2; \
        int c4 = rem & 3; \
        const __nv_bfloat16* src; \
        if (arr == 0)      src = &Ahi[(long)(r0 + row) * KS + (KC) + c4 * 8]; \
        else if (arr == 1) src = &Alo[(long)(r0 + row) * KS + (KC) + c4 * 8]; \
        else if (arr == 2) src = &Bhi[(long)(cb + row) * KS + (KC) + c4 * 8]; \
        else               src = &Blo[(long)(cb + row) * KS + (KC) + c4 * 8]; \
        cp16s(tile + (BUF) * 40960 + arr * 10240 + row * 80 + c4 * 16, src); \
    } \
    asm volatile("cp.async.commit_group;"); \
} while (0)

    FILL_TILE(0, 0);

    for (int kt = 0; kt < KT; kt++) {
        const int p = kt & 1;
        if (kt + 1 < KT) {
            FILL_TILE((kt + 1) * 32, p ^ 1);
            asm volatile("cp.async.wait_group 1;");
        } else {
            asm volatile("cp.async.wait_group 0;");
        }
        __syncthreads();

        const unsigned int bufb = tile + p * 40960;
        const unsigned int Ahib = bufb;
        const unsigned int Alob = bufb + 10240;
        const unsigned int Bhib = bufb + 20480;
        const unsigned int Blob = bufb + 30720;

#pragma unroll
        for (int ks = 0; ks < 2; ks++) {
            unsigned int ahi[2][4], alo[2][4];
#pragma unroll
            for (int mt = 0; mt < 2; mt++) {
                int row = wr * 32 + mt * 16 + (lane & 15);
                unsigned int koff = ((lane >> 4) * 8 + ks * 16) * 2;
                ldm_x4(ahi[mt][0], ahi[mt][1], ahi[mt][2], ahi[mt][3],
                       Ahib + row * 80 + koff);
                ldm_x4(alo[mt][0], alo[mt][1], alo[mt][2], alo[mt][3],
                       Alob + row * 80 + koff);
            }
#pragma unroll
            for (int jn = 0; jn < 4; jn++) {
                int nrow = wc * 64 + jn * 16 + ((lane >> 4) * 8) + (lane & 7);
                unsigned int koff = (ks * 16 + ((lane >> 3) & 1) * 8) * 2;
                unsigned int bhi[4], blo[4];
                ldm_x4(bhi[0], bhi[1], bhi[2], bhi[3], Bhib + nrow * 80 + koff);
                ldm_x4(blo[0], blo[1], blo[2], blo[3], Blob + nrow * 80 + koff);
#pragma unroll
                for (int half = 0; half < 2; half++) {
                    int nt = jn * 2 + half;
#pragma unroll
                    for (int mt = 0; mt < 2; mt++) {
                        mma16816(acc[mt][nt], ahi[mt], bhi + half * 2);
                        mma16816(acc[mt][nt], ahi[mt], blo + half * 2);
                        mma16816(acc[mt][nt], alo[mt], bhi + half * 2);
                    }
                }
            }
        }
        __syncthreads();
    }

#pragma unroll
    for (int mt = 0; mt < 2; mt++)
#pragma unroll
        for (int nt = 0; nt < 8; nt++) {
            int rg = r0 + wr * 32 + mt * 16 + (lane >> 2);
            int cg = cb + wc * 64 + nt * 8 + (lane & 3) * 2;
            float b0 = 0.f, b1 = 0.f;
            if (BIAS) { float2 bv = *(const float2*)&bias[cg]; b0 = bv.x; b1 = bv.y; }
            *(float2*)&C[(long)rg * NC + cg] =
                make_float2(acc[mt][nt][0] + b0, acc[mt][nt][1] + b1);
            *(float2*)&C[(long)(rg + 8) * NC + cg] =
                make_float2(acc[mt][nt][2] + b0, acc[mt][nt][3] + b1);
        }
#undef FILL_TILE
}

__global__ __launch_bounds__(256, 2) void gates_tc_k() {
    tc_gemm<4, KPX, true>(d_Xhi, d_Xlo, d_Ghi, d_Glo, d_gin, NCG, d_bsum);
}
__global__ __launch_bounds__(256, 2) void s_tc_k() {
    tc_gemm<7, KPAD, false>(d_Ahi, d_Alo, d_Bhi, d_Blo, d_S, NCS, nullptr);
}

// ---------------- LSTM recurrence (bf16 hi/lo h output) --------------------------
__global__ __launch_bounds__(800, 1) void lstm_k(const float* __restrict__ Whh_f,
                                                 const float* __restrict__ Whh_b) {
    __shared__ __align__(16) float hs[2][4 * 116];
    const int tid = threadIdx.x;
    const int dir = blockIdx.x >> 6;
    const int b0 = (blockIdx.x & 63) * 4;
    const float* __restrict__ Whh = dir ? Whh_b : Whh_f;

    const int hid = tid >> 3;
    const int sub = tid & 7;
    const int q = sub >> 1;
    const int gh = sub & 1;
    const int hi2 = (q >> 1) & 1;
    const int lo = q & 1;

    ULL w[2][13];
#pragma unroll
    for (int g2 = 0; g2 < 2; g2++) {
        const float* row = Whh + ((gh * 2 + g2) * 100 + hid) * 100 + q * 25;
#pragma unroll
        for (int p = 0; p < 12; p++) w[g2][p] = pack2(row[2 * p], row[2 * p + 1]);
        w[g2][12] = pack2(row[24], 0.0f);
    }
    for (int idx = tid; idx < 2 * 4 * 116; idx += 800) hs[0][idx] = 0.0f;

    const int hq = hid / 25, hr = hid % 25;
    float c = 0.0f;
    float g0, g1;
    {
        int t0 = dir ? (TT - 1) : 0;
        const float* gp = &d_gin[((long)(t0 * 256 + b0 + q)) * NCG + dir * 400 + gh * 200 + hid];
        g0 = gp[0]; g1 = gp[100];
    }
    __syncthreads();

    for (int step = 0; step < TT; ++step) {
        const int t = dir ? (TT - 1 - step) : step;
        const float* hbuf = hs[step & 1];
        float* hnxt = hs[(step + 1) & 1];

        float v[4][2];
#pragma unroll
        for (int b = 0; b < 4; b++) {
            const float* hb = &hbuf[b * 116 + q * 28];
            ULL a0 = 0ull, a1 = 0ull;
#pragma unroll
            for (int m = 0; m < 6; m++) {
                ulonglong2 hp = *(const ulonglong2*)(hb + 4 * m);
                ffma2(a0, w[0][2 * m], hp.x); ffma2(a0, w[0][2 * m + 1], hp.y);
                ffma2(a1, w[1][2 * m], hp.x); ffma2(a1, w[1][2 * m + 1], hp.y);
            }
            {
                ULL ht = *(const ULL*)(hb + 24);
                ffma2(a0, w[0][12], ht); ffma2(a1, w[1][12], ht);
            }
            float2 f0 = unpack2(a0), f1 = unpack2(a1);
            v[b][0] = f0.x + f0.y;
            v[b][1] = f1.x + f1.y;
        }

        float u[2][2];
#pragma unroll
        for (int j = 0; j < 2; j++)
#pragma unroll
            for (int g = 0; g < 2; g++) {
                float keep = hi2 ? v[2 + j][g] : v[j][g];
                float send = hi2 ? v[j][g]     : v[2 + j][g];
                u[j][g] = keep + __shfl_xor_sync(0xFFFFFFFFu, send, 4);
            }
        float s0, s1;
        {
            float k0 = lo ? u[1][0] : u[0][0];
            float e0 = lo ? u[0][0] : u[1][0];
            s0 = k0 + __shfl_xor_sync(0xFFFFFFFFu, e0, 2);
            float k1 = lo ? u[1][1] : u[0][1];
            float e1 = lo ? u[0][1] : u[1][1];
            s1 = k1 + __shfl_xor_sync(0xFFFFFFFFu, e1, 2);
        }

        float uA = g0 + s0;
        float uB = g1 + s1;
        float oA = __shfl_xor_sync(0xFFFFFFFFu, uA, 1);
        float oB = __shfl_xor_sync(0xFFFFFFFFu, uB, 1);
        float pi = gh ? oA : uA;
        float pf = gh ? oB : uB;
        float pg = gh ? uA : oA;
        float po = gh ? uB : oB;
        c = sigf(pf) * c + sigf(pi) * tanhf_fast(pg);
        float h = sigf(po) * tanhf_fast(c);
        if (gh == 0) {
            hnxt[q * 116 + hq * 28 + hr] = h;
            long r = (long)(b0 + q) * TT + t;
            __nv_bfloat16 bh = __float2bfloat16(h);
            __nv_bfloat16 bl = __float2bfloat16(h - __bfloat162float(bh));
            d_Ahi[r * KPAD + dir * 100 + hid] = bh;
            d_Alo[r * KPAD + dir * 100 + hid] = bl;
        }
        {
            int sn = (step + 1 < TT) ? (step + 1) : step;
            int tn = dir ? (TT - 1 - sn) : sn;
            const float* gp = &d_gin[((long)(tn * 256 + b0 + q)) * NCG + dir * 400 + gh * 200 + hid];
            g0 = gp[0]; g1 = gp[100];
        }
        __syncthreads();
    }
}

// ---------------- combine: gather + tanh + (300->3) + softmax --------------------
__global__ __launch_bounds__(256) void combine_k(const int* __restrict__ paths,
                                                 const float* __restrict__ b1,
                                                 const float* __restrict__ W2,
                                                 const float* __restrict__ b2,
                                                 float* __restrict__ out) {
    const int warp = (blockIdx.x * blockDim.x + threadIdx.x) >> 5;
    const int lane = threadIdx.x & 31;
    if (warp >= BB * CC) return;
    const int b = warp / CC;

    const int* p = &paths[warp * 3];
    int p0 = __ldg(p), p1 = __ldg(p + 1), p2 = __ldg(p + 2);
    int i0 = min(max(p0, 0), TT - 1);
    int i1 = min(max(p1, 0), TT - 1);
    int i2 = min(max(p2, 0), TT - 1);

    const float* S0 = &d_S[(long)(b * TT + i0) * NCS];
    const float* S1 = &d_S[(long)(b * TT + i1) * NCS + 300];
    const float* S2 = &d_S[(long)(b * TT + i2) * NCS + 600];

    float z0 = 0.f, z1 = 0.f, z2 = 0.f;
    for (int m = lane; m < MLPD; m += 32) {
        float hv = __ldg(&b1[m]);
        if (p0 >= 0) hv += S0[m];
        if (p1 >= 0) hv += S1[m];
        if (p2 >= 0) hv += S2[m];
        hv = tanhf_fast(hv);
        z0 = fmaf(hv, __ldg(&W2[m * 3 + 0]), z0);
        z1 = fmaf(hv, __ldg(&W2[m * 3 + 1]), z1);
        z2 = fmaf(hv, __ldg(&W2[m * 3 + 2]), z2);
    }
#pragma unroll
    for (int off = 16; off; off >>= 1) {
        z0 += __shfl_xor_sync(0xFFFFFFFFu, z0, off);
        z1 += __shfl_xor_sync(0xFFFFFFFFu, z1, off);
        z2 += __shfl_xor_sync(0xFFFFFFFFu, z2, off);
    }
    if (lane == 0) {
        z0 += __ldg(&b2[0]); z1 += __ldg(&b2[1]); z2 += __ldg(&b2[2]);
        float mx = fmaxf(z0, fmaxf(z1, z2));
        float e0 = __expf(z0 - mx), e1 = __expf(z1 - mx), e2 = __expf(z2 - mx);
        float inv = 1.0f / (e0 + e1 + e2);
        out[warp * 3 + 0] = e0 * inv;
        out[warp * 3 + 1] = e1 * inv;
        out[warp * 3 + 2] = e2 * inv;
    }
}

// -------------------------------- launch -----------------------------------------
extern "C" void kernel_launch(void* const* d_in, const int* in_sizes, int n_in,
                              void* d_out, int out_size) {
    const int*   x     = (const int*)  d_in[0];
    const int*   paths = (const int*)  d_in[1];
    const float* emb   = (const float*)d_in[2];
    const float* Whh_f = (const float*)d_in[4];
    const float* Whh_b = (const float*)d_in[8];
    const float* W1    = (const float*)d_in[11];
    const float* b1    = (const float*)d_in[12];
    const float* W2    = (const float*)d_in[13];
    const float* b2    = (const float*)d_in[14];
    float* out = (float*)d_out;

    cudaFuncSetAttribute(gates_tc_k, cudaFuncAttributeMaxDynamicSharedMemorySize, STC_SMEM);
    cudaFuncSetAttribute(s_tc_k, cudaFuncAttributeMaxDynamicSharedMemorySize, STC_SMEM);

    prep_k<<<256, 256>>>((const float*)d_in[3], (const float*)d_in[7],
                         (const float*)d_in[5], (const float*)d_in[6],
                         (const float*)d_in[9], (const float*)d_in[10], W1);

    xet_k<<<256, 512>>>(x, emb);

    { dim3 g(256, 7); gates_tc_k<<<g, 256, STC_SMEM>>>(); }   // HMMA gates GEMM

    lstm_k<<<128, 800>>>(Whh_f, Whh_b);

    { dim3 g(256, 8); s_tc_k<<<g, 256, STC_SMEM>>>(); }       // HMMA S GEMM

    {
        int warps = BB * CC;
        int blocks = (warps * 32 + 255) / 256;
        combine_k<<<blocks, 256>>>(paths, b1, W2, b2, out);
    }
}